// round 11
// baseline (speedup 1.0000x reference)
#include <cuda_runtime.h>
#include <cuda_bf16.h>
#include <math.h>

#define DEVFN __device__ __forceinline__
#define DG __device__ __align__(128)

constexpr int Bb = 8, Ss = 2048, Dd = 1024, Zz = 128, Nn = 16, Hh = 2048, II = 4096, MPc = 2048;
constexpr int SB = Ss * Bb;
constexpr int NMX = Dd + Zz + Hh + Dd;  // 4224
constexpr float EPS = 1e-3f;
constexpr float SCALING = 0.08838834764831843f;

// ---------------- scratch ----------------
DG float g_xn[(size_t)SB * Dd];
DG float g_u [(size_t)SB * Dd];
DG float g_hx[(size_t)SB * Dd];
DG float g_r [(size_t)SB * Hh];
DG float g_sc[(size_t)Bb * Ss * Ss];
DG float g_h2[(size_t)SB * Dd];
DG float g_ol[(size_t)SB * Dd];
DG __nv_bfloat16 g_xnh[(size_t)SB * Dd],     g_xnl[(size_t)SB * Dd];
DG __nv_bfloat16 g_mxh[(size_t)SB * Dd],     g_mxl[(size_t)SB * Dd];
DG __nv_bfloat16 g_qh [(size_t)Bb * Ss * Zz], g_ql [(size_t)Bb * Ss * Zz];
DG __nv_bfloat16 g_sch[(size_t)Bb * Ss * Ss], g_scl[(size_t)Bb * Ss * Ss];
DG __nv_bfloat16 g_hrh[(size_t)SB * Hh],     g_hrl[(size_t)SB * Hh];
DG __nv_bfloat16 g_olh[(size_t)SB * Dd],     g_oll[(size_t)SB * Dd];
DG __nv_bfloat16 g_inh[(size_t)SB * II],     g_inl[(size_t)SB * II];
DG __nv_bfloat16 g_kh[(size_t)Bb * Ss * Zz], g_kl[(size_t)Bb * Ss * Zz];
DG __nv_bfloat16 g_vh[(size_t)Bb * Hh * Ss], g_vl[(size_t)Bb * Hh * Ss];
DG __nv_bfloat16 g_wvh[(size_t)Hh * Dd],  g_wvl[(size_t)Hh * Dd];
DG __nv_bfloat16 g_wmh[(size_t)NMX * Dd], g_wml[(size_t)NMX * Dd];
DG __nv_bfloat16 g_whh[(size_t)Dd * Hh],  g_whl[(size_t)Dd * Hh];
DG __nv_bfloat16 g_w1h[(size_t)II * Dd],  g_w1l[(size_t)II * Dd];
DG __nv_bfloat16 g_w2h[(size_t)Dd * II],  g_w2l[(size_t)Dd * II];

// ---------------- helpers ----------------
DEVFN float sigm(float x) { return 1.f / (1.f + __expf(-x)); }
DEVFN float silu(float x) { return x / (1.f + __expf(-x)); }
DEVFN void splitStore(__nv_bfloat16* oh, __nv_bfloat16* ol, size_t i, float v) {
    __nv_bfloat16 h = __float2bfloat16(v);
    oh[i] = h;
    ol[i] = __float2bfloat16(v - __bfloat162float(h));
}
DEVFN float warpSum(float v) {
#pragma unroll
    for (int o = 16; o; o >>= 1) v += __shfl_xor_sync(~0u, v, o);
    return v;
}
DEVFN float warpMax(float v) {
#pragma unroll
    for (int o = 16; o; o >>= 1) v = fmaxf(v, __shfl_xor_sync(~0u, v, o));
    return v;
}
DEVFN void blockSum2(float& a, float& b) {
    __shared__ float sa[8], sb_[8];
    float wa = warpSum(a), wb = warpSum(b);
    if ((threadIdx.x & 31) == 0) { sa[threadIdx.x >> 5] = wa; sb_[threadIdx.x >> 5] = wb; }
    __syncthreads();
    a = b = 0.f;
#pragma unroll
    for (int i = 0; i < 8; i++) { a += sa[i]; b += sb_[i]; }
    __syncthreads();
}
DEVFN float blockSum1(float v) {
    __shared__ float s[8];
    float w = warpSum(v);
    if ((threadIdx.x & 31) == 0) s[threadIdx.x >> 5] = w;
    __syncthreads();
    float r = 0.f;
#pragma unroll
    for (int i = 0; i < 8; i++) r += s[i];
    __syncthreads();
    return r;
}
DEVFN float blockMax1(float v) {
    __shared__ float s[8];
    float w = warpMax(v);
    if ((threadIdx.x & 31) == 0) s[threadIdx.x >> 5] = w;
    __syncthreads();
    float r = s[0];
#pragma unroll
    for (int i = 1; i < 8; i++) r = fmaxf(r, s[i]);
    __syncthreads();
    return r;
}

DEVFN void mma16816(float* c, const unsigned* a, const unsigned* b) {
    asm volatile(
        "mma.sync.aligned.m16n8k16.row.col.f32.bf16.bf16.f32 "
        "{%0,%1,%2,%3},{%4,%5,%6,%7},{%8,%9},{%0,%1,%2,%3};"
        : "+f"(c[0]), "+f"(c[1]), "+f"(c[2]), "+f"(c[3])
        : "r"(a[0]), "r"(a[1]), "r"(a[2]), "r"(a[3]), "r"(b[0]), "r"(b[1]));
}
DEVFN void ldsm4(unsigned* r, unsigned addr) {
    asm volatile("ldmatrix.sync.aligned.m8n8.x4.shared.b16 {%0,%1,%2,%3}, [%4];"
                 : "=r"(r[0]), "=r"(r[1]), "=r"(r[2]), "=r"(r[3]) : "r"(addr));
}
DEVFN void cpa16(unsigned dst, const void* src) {
    asm volatile("cp.async.cg.shared.global [%0], [%1], 16;" :: "r"(dst), "l"(src) : "memory");
}
#define CP_COMMIT asm volatile("cp.async.commit_group;" ::: "memory")
#define CP_WAIT0  asm volatile("cp.async.wait_group 0;" ::: "memory")
DEVFN unsigned smem_u32(const void* p) {
    unsigned a;
    asm("{ .reg .u64 t; cvta.to.shared.u64 t, %1; cvt.u32.u64 %0, t; }" : "=r"(a) : "l"(p));
    return a;
}

// ---------------- elementwise ----------------
__global__ __launch_bounds__(256) void k_ln1(const float* __restrict__ x,
                                             const float* __restrict__ sc,
                                             const float* __restrict__ bi) {
    int m = blockIdx.x, b = m / Ss, s = m % Ss, t = threadIdx.x;
    const float* xr = x + (size_t)m * Dd;
    float v[4], su = 0.f, sq = 0.f;
#pragma unroll
    for (int i = 0; i < 4; i++) { float f = xr[t + 256 * i]; v[i] = f; su += f; sq += f * f; }
    blockSum2(su, sq);
    float mu = su * (1.f / Dd), inv = rsqrtf(sq * (1.f / Dd) - mu * mu + EPS);
    size_t base = (size_t)(s * Bb + b) * Dd;
#pragma unroll
    for (int i = 0; i < 4; i++) {
        int d = t + 256 * i;
        float val = (v[i] - mu) * inv * sc[d] + bi[d];
        g_xn[base + d] = val;
        splitStore(g_xnh, g_xnl, base + d, val);
    }
}

__global__ __launch_bounds__(256) void k_ema(const float* __restrict__ de, const float* __restrict__ al,
                                             const float* __restrict__ be, const float* __restrict__ ga,
                                             const float* __restrict__ om) {
    int t = threadIdx.x, lane = t & 15;
    int P = blockIdx.x * 16 + (t >> 4), b = P / Dd, d = P % Dd;
    int pi = d * Nn + lane;
    float p = sigm(de[pi]);
    float q = 1.f - p * sigm(al[pi]);
    float coef = p * be[pi] * ga[pi] * 0.25f;
    float w = om[d];
    const float* xp = g_xn + (size_t)b * Dd + d;
    size_t obase = (size_t)b * Dd + d;
    float s = 0.f;
    for (int l = 0; l < Ss; l++) {
        float xv = xp[(size_t)l * (Bb * Dd)];
        s = fmaf(q, s, xv);
        float r = coef * s;
        r += __shfl_xor_sync(~0u, r, 1);
        r += __shfl_xor_sync(~0u, r, 2);
        r += __shfl_xor_sync(~0u, r, 4);
        r += __shfl_xor_sync(~0u, r, 8);
        if (lane == 0) {
            float val = silu(r + xv * w);
            splitStore(g_mxh, g_mxl, obase + (size_t)l * (Bb * Dd), val);
        }
    }
}

__global__ __launch_bounds__(256) void k_softmax() {
    size_t rbase = (size_t)blockIdx.x * Ss;
    const float* rp = g_sc + rbase;
    int t = threadIdx.x;
    float v[8], mx = -1e30f;
#pragma unroll
    for (int i = 0; i < 8; i++) { v[i] = rp[t + 256 * i]; mx = fmaxf(mx, v[i]); }
    mx = blockMax1(mx);
    float su = 0.f;
#pragma unroll
    for (int i = 0; i < 8; i++) { v[i] = __expf(v[i] - mx); su += v[i]; }
    su = blockSum1(su);
    float inv = 1.f / su;
#pragma unroll
    for (int i = 0; i < 8; i++)
        splitStore(g_sch, g_scl, rbase + t + 256 * i, v[i] * inv);
}

__global__ __launch_bounds__(256) void k_gateln(const float* __restrict__ sc,
                                                const float* __restrict__ bi) {
    int m = blockIdx.x, s = m >> 3, b = m & 7, t = threadIdx.x;
    size_t base = (size_t)m * Dd;
    float g[4], su = 0.f, sq = 0.f;
#pragma unroll
    for (int i = 0; i < 4; i++) {
        int d = t + 256 * i;
        float xn = g_xn[base + d];
        float val = xn + g_u[base + d] * (g_h2[base + d] - xn);
        g[i] = val; su += val; sq += val * val;
    }
    blockSum2(su, sq);
    float mu = su * (1.f / Dd), inv = rsqrtf(sq * (1.f / Dd) - mu * mu + EPS);
    size_t ob = ((size_t)b * Ss + s) * Dd;
#pragma unroll
    for (int i = 0; i < 4; i++) {
        int d = t + 256 * i;
        float val = (g[i] - mu) * inv * sc[d] + bi[d];
        g_ol[ob + d] = val;
        splitStore(g_olh, g_oll, ob + d, val);
    }
}

__global__ __launch_bounds__(256) void k_wt(const float* __restrict__ W,
                                            __nv_bfloat16* __restrict__ oh,
                                            __nv_bfloat16* __restrict__ ol, int K, int N) {
    __shared__ float tl[32][33];
    int n0 = blockIdx.x * 32, k0 = blockIdx.y * 32;
    int tx = threadIdx.x & 31, ty = threadIdx.x >> 5;
#pragma unroll
    for (int i = 0; i < 4; i++) tl[ty + i * 8][tx] = W[(size_t)(k0 + ty + i * 8) * N + n0 + tx];
    __syncthreads();
#pragma unroll
    for (int i = 0; i < 4; i++) {
        int ny = ty + i * 8;
        splitStore(oh, ol, (size_t)(n0 + ny) * K + k0 + tx, tl[tx][ny]);
    }
}

// ================= mma.sync bf16-split GEMM (TM=256,TN=128, KT=64) =================
struct TG {
    const __nv_bfloat16* Ah; const __nv_bfloat16* Al;
    const __nv_bfloat16* Bh; const __nv_bfloat16* Bl;
    const float* bias; const float* aux; const float* aux2;
    float* out;
    int K, Nv;
    long long sA, sB;
};

enum { MP_V = 0, MP_BASE, MP_SC, MP_HR, MP_H2, MP_RELU, MP_FIN };

template<int EP>
DEVFN void epiM(const TG& p, int bz, int m, int n, float acc) {
    if (EP == MP_V) {
        float v = silu(acc + p.bias[n]);
        int s = m >> 3, b = m & 7;
        splitStore(g_vh, g_vl, ((size_t)(b * Hh + n)) * Ss + s, v);
    } else if (EP == MP_BASE) {
        float a = acc + p.bias[n];
        if (n < Dd) {
            g_u[(size_t)m * Dd + n] = sigm(a);
        } else if (n < Dd + Zz) {
            float z = silu(a); int zi = n - Dd;
            int s = m >> 3, b = m & 7;
            size_t o = ((size_t)(b * Ss + s)) * Zz + zi;
            splitStore(g_qh, g_ql, o, z * p.aux[zi] + p.aux2[zi]);
            splitStore(g_kh, g_kl, o, z * p.aux[Zz + zi] + p.aux2[Zz + zi]);
        } else if (n < Dd + Zz + Hh) {
            g_r[(size_t)m * Hh + (n - Dd - Zz)] = silu(a);
        } else {
            g_hx[(size_t)m * Dd + (n - Dd - Zz - Hh)] = a;
        }
    } else if (EP == MP_SC) {
        g_sc[((size_t)bz * Ss + m) * Ss + n] = acc * SCALING + p.aux[MPc - 1 + n - m];
    } else if (EP == MP_HR) {
        size_t o = ((size_t)(m * Bb + bz)) * Hh + n;
        splitStore(g_hrh, g_hrl, o, acc * g_r[o]);
    } else if (EP == MP_H2) {
        g_h2[(size_t)m * Dd + n] = silu(acc + p.bias[n] + g_hx[(size_t)m * Dd + n]);
    } else if (EP == MP_RELU) {
        splitStore(g_inh, g_inl, (size_t)m * II + n, fmaxf(acc + p.bias[n], 0.f));
    } else {
        p.out[(size_t)m * Dd + n] = acc + p.bias[n] + g_ol[(size_t)m * Dd + n];
    }
}

// CTA 256x128, warp 64x64 (4m x 2n), K-chunk 64 bf16, double-buffered, cp.async-fed.
// smem row = 128B; 16B-granular swizzle: unit' = unit ^ (row & 7).
template<int EP>
__global__ void __launch_bounds__(256, 1) k_mgemm(TG p) {
    constexpr int TM = 256, TN = 128;
    constexpr int ASZ = TM * 128;             // 32768 bytes per A matrix (hi or lo)
    constexpr int BSZ = TN * 128;             // 16384
    constexpr int STGB = 2 * ASZ + 2 * BSZ;   // 98304
    constexpr int KT = 64;

    extern __shared__ char sm[];
    const unsigned sb = smem_u32(sm);

    const int t = threadIdx.x, lane = t & 31, wid = t >> 5;
    const int wm = wid & 3, wn = wid >> 2;
    const int g = lane >> 2, tig = lane & 3;
    const int bz = blockIdx.z;
    const int m0 = blockIdx.y * TM, n0 = blockIdx.x * TN;
    const __nv_bfloat16* Ahp = p.Ah + (size_t)bz * (size_t)p.sA;
    const __nv_bfloat16* Alp = p.Al + (size_t)bz * (size_t)p.sA;
    const __nv_bfloat16* Bhp = p.Bh + (size_t)bz * (size_t)p.sB;
    const __nv_bfloat16* Blp = p.Bl + (size_t)bz * (size_t)p.sB;
    const int K = p.K;
    const int nst = K / KT;
    const int Nv = p.Nv;

    // ldmatrix per-lane fragment bases
    const int matq = lane >> 3, r8 = lane & 7;
    const int amq = matq >> 1, bmq = matq & 1;
    unsigned aBase[4]; int aswz[4];
#pragma unroll
    for (int mi = 0; mi < 4; mi++) {
        int arow = wm * 64 + mi * 16 + (matq & 1) * 8 + r8;
        aBase[mi] = sb + arow * 128;
        aswz[mi] = arow & 7;
    }
    unsigned bBase[2][2]; int bswz[2][2];
#pragma unroll
    for (int nh = 0; nh < 2; nh++)
#pragma unroll
        for (int njp = 0; njp < 2; njp++) {
            int brow = wn * 64 + nh * 32 + njp * 16 + (matq >> 1) * 8 + r8;
            bBase[nh][njp] = sb + 2 * ASZ + brow * 128;
            bswz[nh][njp] = brow & 7;
        }

    float acc[4][8][4];
#pragma unroll
    for (int i = 0; i < 4; i++)
#pragma unroll
        for (int j = 0; j < 8; j++)
#pragma unroll
            for (int r = 0; r < 4; r++) acc[i][j][r] = 0.f;

    auto CPA = [&](int k0, int buf) {
        unsigned ah = sb + buf * STGB, al = ah + ASZ;
#pragma unroll
        for (int j = 0; j < 8; j++) {
            int idx = t + 256 * j;
            int row = idx >> 3, q = idx & 7;
            unsigned off = row * 128 + ((q ^ (row & 7)) << 4);
            size_t go = (size_t)(m0 + row) * K + k0 + q * 8;
            cpa16(ah + off, Ahp + go);
            cpa16(al + off, Alp + go);
        }
    };
    auto CPB = [&](int k0, int buf) {
        unsigned bh = sb + buf * STGB + 2 * ASZ, bl = bh + BSZ;
#pragma unroll
        for (int j = 0; j < 4; j++) {
            int idx = t + 256 * j;
            int row = idx >> 3, q = idx & 7;
            int rn = n0 + row; if (rn >= Nv) rn = Nv - 1;
            unsigned off = row * 128 + ((q ^ (row & 7)) << 4);
            size_t go = (size_t)rn * K + k0 + q * 8;
            cpa16(bh + off, Bhp + go);
            cpa16(bl + off, Blp + go);
        }
    };

    auto COMPUTE = [&](int buf) {
        const unsigned off = buf * STGB;
#pragma unroll
        for (int kk = 0; kk < 4; kk++) {
            unsigned Ah[4][4], Al[4][4];
#pragma unroll
            for (int mi = 0; mi < 4; mi++) {
                unsigned ao = off + (((kk * 2 + amq) ^ aswz[mi]) << 4);
                ldsm4(Ah[mi], aBase[mi] + ao);
                ldsm4(Al[mi], aBase[mi] + ao + ASZ);
            }
#pragma unroll
            for (int nh = 0; nh < 2; nh++) {
                unsigned Bh4[2][4], Bl4[2][4];
#pragma unroll
                for (int njp = 0; njp < 2; njp++) {
                    unsigned bo = off + (((kk * 2 + bmq) ^ bswz[nh][njp]) << 4);
                    ldsm4(Bh4[njp], bBase[nh][njp] + bo);
                    ldsm4(Bl4[njp], bBase[nh][njp] + bo + BSZ);
                }
#pragma unroll
                for (int nj = 0; nj < 4; nj++) {
                    int njp = nj >> 1, hi = (nj & 1) * 2;
                    unsigned bfh[2] = { Bh4[njp][hi], Bh4[njp][hi + 1] };
                    unsigned bfl[2] = { Bl4[njp][hi], Bl4[njp][hi + 1] };
#pragma unroll
                    for (int mi = 0; mi < 4; mi++) {
                        float* c = acc[mi][nh * 4 + nj];
                        mma16816(c, Ah[mi], bfh);
                        mma16816(c, Al[mi], bfh);
                        mma16816(c, Ah[mi], bfl);
                    }
                }
            }
        }
    };

    // prologue
    CPA(0, 0); CPB(0, 0); CP_COMMIT;
    CP_WAIT0;
    __syncthreads();

    for (int s = 0; s < nst; s++) {
        if (s + 1 < nst) { CPA((s + 1) * KT, (s + 1) & 1); CPB((s + 1) * KT, (s + 1) & 1); CP_COMMIT; }
        COMPUTE(s & 1);
        if (s + 1 < nst) CP_WAIT0;
        __syncthreads();
    }

#pragma unroll
    for (int mi = 0; mi < 4; mi++)
#pragma unroll
        for (int ni = 0; ni < 8; ni++) {
            int row0 = m0 + wm * 64 + mi * 16 + g;
            int col0 = n0 + wn * 64 + ni * 8 + 2 * tig;
            float* c = acc[mi][ni];
            if (col0 < Nv)     epiM<EP>(p, bz, row0,     col0,     c[0]);
            if (col0 + 1 < Nv) epiM<EP>(p, bz, row0,     col0 + 1, c[1]);
            if (col0 < Nv)     epiM<EP>(p, bz, row0 + 8, col0,     c[2]);
            if (col0 + 1 < Nv) epiM<EP>(p, bz, row0 + 8, col0 + 1, c[3]);
        }
}

// ---------------- launch ----------------
constexpr int SMM = 2 * (2 * 256 * 128 + 2 * 128 * 128);  // 196608

extern "C" void kernel_launch(void* const* d_in, const int* in_sizes, int n_in,
                              void* d_out, int out_size) {
    (void)in_sizes; (void)n_in; (void)out_size;
    const float* x    = (const float*)d_in[0];
    const float* ln_s = (const float*)d_in[1];
    const float* ln_b = (const float*)d_in[2];
    const float* v_w  = (const float*)d_in[3];
    const float* v_b  = (const float*)d_in[4];
    const float* mx_w = (const float*)d_in[5];
    const float* mx_b = (const float*)d_in[6];
    const float* h_w  = (const float*)d_in[7];
    const float* h_b  = (const float*)d_in[8];
    const float* gamma= (const float*)d_in[9];
    const float* beta = (const float*)d_in[10];
    const float* rel  = (const float*)d_in[11];
    const float* e_d  = (const float*)d_in[12];
    const float* e_a  = (const float*)d_in[13];
    const float* e_b  = (const float*)d_in[14];
    const float* e_g  = (const float*)d_in[15];
    const float* e_o  = (const float*)d_in[16];
    const float* f_s  = (const float*)d_in[17];
    const float* f_b  = (const float*)d_in[18];
    const float* w1   = (const float*)d_in[19];
    const float* b1   = (const float*)d_in[20];
    const float* w2   = (const float*)d_in[21];
    const float* b2   = (const float*)d_in[22];

    __nv_bfloat16 *p_xnh, *p_xnl, *p_mxh, *p_mxl, *p_qh, *p_ql, *p_sch, *p_scl;
    __nv_bfloat16 *p_hrh, *p_hrl, *p_olh, *p_oll, *p_inh, *p_inl;
    __nv_bfloat16 *p_kh, *p_kl, *p_vh, *p_vl;
    __nv_bfloat16 *p_wvh, *p_wvl, *p_wmh, *p_wml, *p_whh, *p_whl, *p_w1h, *p_w1l, *p_w2h, *p_w2l;
    cudaGetSymbolAddress((void**)&p_xnh, g_xnh);
    cudaGetSymbolAddress((void**)&p_xnl, g_xnl);
    cudaGetSymbolAddress((void**)&p_mxh, g_mxh);
    cudaGetSymbolAddress((void**)&p_mxl, g_mxl);
    cudaGetSymbolAddress((void**)&p_qh,  g_qh);
    cudaGetSymbolAddress((void**)&p_ql,  g_ql);
    cudaGetSymbolAddress((void**)&p_sch, g_sch);
    cudaGetSymbolAddress((void**)&p_scl, g_scl);
    cudaGetSymbolAddress((void**)&p_hrh, g_hrh);
    cudaGetSymbolAddress((void**)&p_hrl, g_hrl);
    cudaGetSymbolAddress((void**)&p_olh, g_olh);
    cudaGetSymbolAddress((void**)&p_oll, g_oll);
    cudaGetSymbolAddress((void**)&p_inh, g_inh);
    cudaGetSymbolAddress((void**)&p_inl, g_inl);
    cudaGetSymbolAddress((void**)&p_kh, g_kh);
    cudaGetSymbolAddress((void**)&p_kl, g_kl);
    cudaGetSymbolAddress((void**)&p_vh, g_vh);
    cudaGetSymbolAddress((void**)&p_vl, g_vl);
    cudaGetSymbolAddress((void**)&p_wvh, g_wvh);
    cudaGetSymbolAddress((void**)&p_wvl, g_wvl);
    cudaGetSymbolAddress((void**)&p_wmh, g_wmh);
    cudaGetSymbolAddress((void**)&p_wml, g_wml);
    cudaGetSymbolAddress((void**)&p_whh, g_whh);
    cudaGetSymbolAddress((void**)&p_whl, g_whl);
    cudaGetSymbolAddress((void**)&p_w1h, g_w1h);
    cudaGetSymbolAddress((void**)&p_w1l, g_w1l);
    cudaGetSymbolAddress((void**)&p_w2h, g_w2h);
    cudaGetSymbolAddress((void**)&p_w2l, g_w2l);

    cudaFuncSetAttribute(k_mgemm<MP_V>,    cudaFuncAttributeMaxDynamicSharedMemorySize, SMM);
    cudaFuncSetAttribute(k_mgemm<MP_BASE>, cudaFuncAttributeMaxDynamicSharedMemorySize, SMM);
    cudaFuncSetAttribute(k_mgemm<MP_SC>,   cudaFuncAttributeMaxDynamicSharedMemorySize, SMM);
    cudaFuncSetAttribute(k_mgemm<MP_HR>,   cudaFuncAttributeMaxDynamicSharedMemorySize, SMM);
    cudaFuncSetAttribute(k_mgemm<MP_H2>,   cudaFuncAttributeMaxDynamicSharedMemorySize, SMM);
    cudaFuncSetAttribute(k_mgemm<MP_RELU>, cudaFuncAttributeMaxDynamicSharedMemorySize, SMM);
    cudaFuncSetAttribute(k_mgemm<MP_FIN>,  cudaFuncAttributeMaxDynamicSharedMemorySize, SMM);

    k_wt<<<dim3(Hh / 32, Dd / 32), 256>>>(v_w, p_wvh, p_wvl, Dd, Hh);
    k_wt<<<dim3(NMX / 32, Dd / 32), 256>>>(mx_w, p_wmh, p_wml, Dd, NMX);
    k_wt<<<dim3(Dd / 32, Hh / 32), 256>>>(h_w, p_whh, p_whl, Hh, Dd);
    k_wt<<<dim3(II / 32, Dd / 32), 256>>>(w1, p_w1h, p_w1l, Dd, II);
    k_wt<<<dim3(Dd / 32, II / 32), 256>>>(w2, p_w2h, p_w2l, II, Dd);

    k_ln1<<<SB, 256>>>(x, ln_s, ln_b);
    k_ema<<<(Bb * Dd) / 16, 256>>>(e_d, e_a, e_b, e_g, e_o);

    TG p;
    // v = silu(xn @ v_w + v_b) -> v^T bf16 split
    p = {p_xnh, p_xnl, p_wvh, p_wvl, v_b, nullptr, nullptr, nullptr, Dd, Hh, 0, 0};
    k_mgemm<MP_V><<<dim3(Hh / 128, SB / 256, 1), 256, SMM>>>(p);
    // base = mx @ mx_w + mx_b -> u,(q,k),r,hx   (NMX = 33 * 128 exact)
    p = {p_mxh, p_mxl, p_wmh, p_wml, mx_b, gamma, beta, nullptr, Dd, NMX, 0, 0};
    k_mgemm<MP_BASE><<<dim3(NMX / 128, SB / 256, 1), 256, SMM>>>(p);
    // scores = scaling * q @ k^T + relpos   (batched)
    p = {p_qh, p_ql, p_kh, p_kl, nullptr, rel, nullptr, nullptr, Zz, Ss, (long long)Ss * Zz, (long long)Ss * Zz};
    k_mgemm<MP_SC><<<dim3(Ss / 128, Ss / 256, Bb), 256, SMM>>>(p);
    k_softmax<<<Bb * Ss, 256>>>();
    // hr = (attn @ v) * r   (batched, fused)
    p = {p_sch, p_scl, p_vh, p_vl, nullptr, nullptr, nullptr, nullptr, Ss, Hh, (long long)Ss * Ss, (long long)Hh * Ss};
    k_mgemm<MP_HR><<<dim3(Hh / 128, Ss / 256, Bb), 256, SMM>>>(p);
    // h2 = silu(hx + hr @ h_w + h_b)
    p = {p_hrh, p_hrl, p_whh, p_whl, h_b, nullptr, nullptr, nullptr, Hh, Dd, 0, 0};
    k_mgemm<MP_H2><<<dim3(Dd / 128, SB / 256, 1), 256, SMM>>>(p);
    k_gateln<<<SB, 256>>>(f_s, f_b);
    // FFN
    p = {p_olh, p_oll, p_w1h, p_w1l, b1, nullptr, nullptr, nullptr, Dd, II, 0, 0};
    k_mgemm<MP_RELU><<<dim3(II / 128, SB / 256, 1), 256, SMM>>>(p);
    p = {p_inh, p_inl, p_w2h, p_w2l, b2, nullptr, nullptr, (float*)d_out, II, Dd, 0, 0};
    k_mgemm<MP_FIN><<<dim3(Dd / 128, SB / 256, 1), 256, SMM>>>(p);
}

// round 12
// speedup vs baseline: 1.1878x; 1.1878x over previous
#include <cuda_runtime.h>
#include <cuda_bf16.h>
#include <cuda_fp16.h>
#include <math.h>

#define DEVFN __device__ __forceinline__
#define DG __device__ __align__(128)

constexpr int Bb = 8, Ss = 2048, Dd = 1024, Zz = 128, Nn = 16, Hh = 2048, II = 4096, MPc = 2048;
constexpr int SB = Ss * Bb;
constexpr int NMX = Dd + Zz + Hh + Dd;  // 4224
constexpr float EPS = 1e-3f;
constexpr float SCALING = 0.08838834764831843f;

// ---------------- scratch ----------------
DG float g_xn[(size_t)SB * Dd];
DG float g_u [(size_t)SB * Dd];
DG float g_hx[(size_t)SB * Dd];
DG float g_r [(size_t)SB * Hh];
DG float g_sc[(size_t)Bb * Ss * Ss];
DG float g_h2[(size_t)SB * Dd];
DG float g_ol[(size_t)SB * Dd];
// fp16 split A operands (2-term GEMMs)
DG __half g_xnh[(size_t)SB * Dd],      g_xnl[(size_t)SB * Dd];
DG __half g_sch[(size_t)Bb * Ss * Ss], g_scl[(size_t)Bb * Ss * Ss];
DG __half g_hrh[(size_t)SB * Hh],      g_hrl[(size_t)SB * Hh];
DG __half g_olh[(size_t)SB * Dd],      g_oll[(size_t)SB * Dd];
DG __half g_inh[(size_t)SB * II],      g_inl[(size_t)SB * II];
// fp16 hi-only B operands (2-term GEMMs)
DG __half g_vh [(size_t)Bb * Hh * Ss];
DG __half g_wvh[(size_t)Hh * Dd];
DG __half g_whh[(size_t)Dd * Hh];
DG __half g_w1h[(size_t)II * Dd];
DG __half g_w2h[(size_t)Dd * II];
// bf16 split operands (3-term GEMMs: mx-proj, scores)
DG __nv_bfloat16 g_mxh[(size_t)SB * Dd],      g_mxl[(size_t)SB * Dd];
DG __nv_bfloat16 g_qh [(size_t)Bb * Ss * Zz], g_ql [(size_t)Bb * Ss * Zz];
DG __nv_bfloat16 g_kh [(size_t)Bb * Ss * Zz], g_kl [(size_t)Bb * Ss * Zz];
DG __nv_bfloat16 g_wmh[(size_t)NMX * Dd],     g_wml[(size_t)NMX * Dd];

// ---------------- helpers ----------------
DEVFN float sigm(float x) { return 1.f / (1.f + __expf(-x)); }
DEVFN float silu(float x) { return x / (1.f + __expf(-x)); }
DEVFN void splitB(__nv_bfloat16* oh, __nv_bfloat16* ol, size_t i, float v) {
    __nv_bfloat16 h = __float2bfloat16(v);
    oh[i] = h;
    ol[i] = __float2bfloat16(v - __bfloat162float(h));
}
DEVFN void splitH(__half* oh, __half* ol, size_t i, float v) {
    __half h = __float2half_rn(v);
    oh[i] = h;
    ol[i] = __float2half_rn(v - __half2float(h));
}
DEVFN float warpSum(float v) {
#pragma unroll
    for (int o = 16; o; o >>= 1) v += __shfl_xor_sync(~0u, v, o);
    return v;
}
DEVFN float warpMax(float v) {
#pragma unroll
    for (int o = 16; o; o >>= 1) v = fmaxf(v, __shfl_xor_sync(~0u, v, o));
    return v;
}
DEVFN void blockSum2(float& a, float& b) {
    __shared__ float sa[8], sb_[8];
    float wa = warpSum(a), wb = warpSum(b);
    if ((threadIdx.x & 31) == 0) { sa[threadIdx.x >> 5] = wa; sb_[threadIdx.x >> 5] = wb; }
    __syncthreads();
    a = b = 0.f;
#pragma unroll
    for (int i = 0; i < 8; i++) { a += sa[i]; b += sb_[i]; }
    __syncthreads();
}
DEVFN float blockSum1(float v) {
    __shared__ float s[8];
    float w = warpSum(v);
    if ((threadIdx.x & 31) == 0) s[threadIdx.x >> 5] = w;
    __syncthreads();
    float r = 0.f;
#pragma unroll
    for (int i = 0; i < 8; i++) r += s[i];
    __syncthreads();
    return r;
}
DEVFN float blockMax1(float v) {
    __shared__ float s[8];
    float w = warpMax(v);
    if ((threadIdx.x & 31) == 0) s[threadIdx.x >> 5] = w;
    __syncthreads();
    float r = s[0];
#pragma unroll
    for (int i = 1; i < 8; i++) r = fmaxf(r, s[i]);
    __syncthreads();
    return r;
}

template<typename ET> struct MMA;
template<> struct MMA<__nv_bfloat16> {
    static DEVFN void run(float* c, const unsigned* a, const unsigned* b) {
        asm volatile(
            "mma.sync.aligned.m16n8k16.row.col.f32.bf16.bf16.f32 "
            "{%0,%1,%2,%3},{%4,%5,%6,%7},{%8,%9},{%0,%1,%2,%3};"
            : "+f"(c[0]), "+f"(c[1]), "+f"(c[2]), "+f"(c[3])
            : "r"(a[0]), "r"(a[1]), "r"(a[2]), "r"(a[3]), "r"(b[0]), "r"(b[1]));
    }
};
template<> struct MMA<__half> {
    static DEVFN void run(float* c, const unsigned* a, const unsigned* b) {
        asm volatile(
            "mma.sync.aligned.m16n8k16.row.col.f32.f16.f16.f32 "
            "{%0,%1,%2,%3},{%4,%5,%6,%7},{%8,%9},{%0,%1,%2,%3};"
            : "+f"(c[0]), "+f"(c[1]), "+f"(c[2]), "+f"(c[3])
            : "r"(a[0]), "r"(a[1]), "r"(a[2]), "r"(a[3]), "r"(b[0]), "r"(b[1]));
    }
};

DEVFN void ldsm4(unsigned* r, unsigned addr) {
    asm volatile("ldmatrix.sync.aligned.m8n8.x4.shared.b16 {%0,%1,%2,%3}, [%4];"
                 : "=r"(r[0]), "=r"(r[1]), "=r"(r[2]), "=r"(r[3]) : "r"(addr));
}
DEVFN void cpa16(unsigned dst, const void* src) {
    asm volatile("cp.async.cg.shared.global [%0], [%1], 16;" :: "r"(dst), "l"(src) : "memory");
}
#define CP_COMMIT asm volatile("cp.async.commit_group;" ::: "memory")
#define CP_WAIT0  asm volatile("cp.async.wait_group 0;" ::: "memory")
DEVFN unsigned smem_u32(const void* p) {
    unsigned a;
    asm("{ .reg .u64 t; cvta.to.shared.u64 t, %1; cvt.u32.u64 %0, t; }" : "=r"(a) : "l"(p));
    return a;
}

// ---------------- elementwise ----------------
__global__ __launch_bounds__(256) void k_ln1(const float* __restrict__ x,
                                             const float* __restrict__ sc,
                                             const float* __restrict__ bi) {
    int m = blockIdx.x, b = m / Ss, s = m % Ss, t = threadIdx.x;
    const float* xr = x + (size_t)m * Dd;
    float v[4], su = 0.f, sq = 0.f;
#pragma unroll
    for (int i = 0; i < 4; i++) { float f = xr[t + 256 * i]; v[i] = f; su += f; sq += f * f; }
    blockSum2(su, sq);
    float mu = su * (1.f / Dd), inv = rsqrtf(sq * (1.f / Dd) - mu * mu + EPS);
    size_t base = (size_t)(s * Bb + b) * Dd;
#pragma unroll
    for (int i = 0; i < 4; i++) {
        int d = t + 256 * i;
        float val = (v[i] - mu) * inv * sc[d] + bi[d];
        g_xn[base + d] = val;
        splitH(g_xnh, g_xnl, base + d, val);
    }
}

__global__ __launch_bounds__(256) void k_ema(const float* __restrict__ de, const float* __restrict__ al,
                                             const float* __restrict__ be, const float* __restrict__ ga,
                                             const float* __restrict__ om) {
    int t = threadIdx.x, lane = t & 15;
    int P = blockIdx.x * 16 + (t >> 4), b = P / Dd, d = P % Dd;
    int pi = d * Nn + lane;
    float p = sigm(de[pi]);
    float q = 1.f - p * sigm(al[pi]);
    float coef = p * be[pi] * ga[pi] * 0.25f;
    float w = om[d];
    const float* xp = g_xn + (size_t)b * Dd + d;
    size_t obase = (size_t)b * Dd + d;
    float s = 0.f;
    for (int l = 0; l < Ss; l++) {
        float xv = xp[(size_t)l * (Bb * Dd)];
        s = fmaf(q, s, xv);
        float r = coef * s;
        r += __shfl_xor_sync(~0u, r, 1);
        r += __shfl_xor_sync(~0u, r, 2);
        r += __shfl_xor_sync(~0u, r, 4);
        r += __shfl_xor_sync(~0u, r, 8);
        if (lane == 0) {
            float val = silu(r + xv * w);
            splitB(g_mxh, g_mxl, obase + (size_t)l * (Bb * Dd), val);
        }
    }
}

__global__ __launch_bounds__(256) void k_softmax() {
    size_t rbase = (size_t)blockIdx.x * Ss;
    const float* rp = g_sc + rbase;
    int t = threadIdx.x;
    float v[8], mx = -1e30f;
#pragma unroll
    for (int i = 0; i < 8; i++) { v[i] = rp[t + 256 * i]; mx = fmaxf(mx, v[i]); }
    mx = blockMax1(mx);
    float su = 0.f;
#pragma unroll
    for (int i = 0; i < 8; i++) { v[i] = __expf(v[i] - mx); su += v[i]; }
    su = blockSum1(su);
    float inv = 1.f / su;
#pragma unroll
    for (int i = 0; i < 8; i++)
        splitH(g_sch, g_scl, rbase + t + 256 * i, v[i] * inv);
}

__global__ __launch_bounds__(256) void k_gateln(const float* __restrict__ sc,
                                                const float* __restrict__ bi) {
    int m = blockIdx.x, s = m >> 3, b = m & 7, t = threadIdx.x;
    size_t base = (size_t)m * Dd;
    float g[4], su = 0.f, sq = 0.f;
#pragma unroll
    for (int i = 0; i < 4; i++) {
        int d = t + 256 * i;
        float xn = g_xn[base + d];
        float val = xn + g_u[base + d] * (g_h2[base + d] - xn);
        g[i] = val; su += val; sq += val * val;
    }
    blockSum2(su, sq);
    float mu = su * (1.f / Dd), inv = rsqrtf(sq * (1.f / Dd) - mu * mu + EPS);
    size_t ob = ((size_t)b * Ss + s) * Dd;
#pragma unroll
    for (int i = 0; i < 4; i++) {
        int d = t + 256 * i;
        float val = (g[i] - mu) * inv * sc[d] + bi[d];
        g_ol[ob + d] = val;
        splitH(g_olh, g_oll, ob + d, val);
    }
}

// weight transpose+convert: LO=true -> bf16 hi/lo, LO=false -> fp16 hi only
template<typename T, bool LO>
__global__ __launch_bounds__(256) void k_wt(const float* __restrict__ W,
                                            T* __restrict__ oh,
                                            T* __restrict__ ol, int K, int N) {
    __shared__ float tl[32][33];
    int n0 = blockIdx.x * 32, k0 = blockIdx.y * 32;
    int tx = threadIdx.x & 31, ty = threadIdx.x >> 5;
#pragma unroll
    for (int i = 0; i < 4; i++) tl[ty + i * 8][tx] = W[(size_t)(k0 + ty + i * 8) * N + n0 + tx];
    __syncthreads();
#pragma unroll
    for (int i = 0; i < 4; i++) {
        int ny = ty + i * 8;
        float v = tl[tx][ny];
        size_t o = (size_t)(n0 + ny) * K + k0 + tx;
        T h = (T)v;
        oh[o] = h;
        if (LO) ol[o] = (T)(v - (float)h);
    }
}

// ================= mma.sync split GEMM (TM=256,TN=128, KT=64) =================
struct TG {
    const void* Ah; const void* Al;
    const void* Bh; const void* Bl;
    const float* bias; const float* aux; const float* aux2;
    float* out;
    int K, Nv;
    long long sA, sB;
};

enum { MP_V = 0, MP_BASE, MP_SC, MP_HR, MP_H2, MP_RELU, MP_FIN };

template<int EP>
DEVFN void epiM(const TG& p, int bz, int m, int n, float acc) {
    if (EP == MP_V) {
        float v = silu(acc + p.bias[n]);
        int s = m >> 3, b = m & 7;
        g_vh[((size_t)(b * Hh + n)) * Ss + s] = __float2half_rn(v);
    } else if (EP == MP_BASE) {
        float a = acc + p.bias[n];
        if (n < Dd) {
            g_u[(size_t)m * Dd + n] = sigm(a);
        } else if (n < Dd + Zz) {
            float z = silu(a); int zi = n - Dd;
            int s = m >> 3, b = m & 7;
            size_t o = ((size_t)(b * Ss + s)) * Zz + zi;
            splitB(g_qh, g_ql, o, z * p.aux[zi] + p.aux2[zi]);
            splitB(g_kh, g_kl, o, z * p.aux[Zz + zi] + p.aux2[Zz + zi]);
        } else if (n < Dd + Zz + Hh) {
            g_r[(size_t)m * Hh + (n - Dd - Zz)] = silu(a);
        } else {
            g_hx[(size_t)m * Dd + (n - Dd - Zz - Hh)] = a;
        }
    } else if (EP == MP_SC) {
        g_sc[((size_t)bz * Ss + m) * Ss + n] = acc * SCALING + p.aux[MPc - 1 + n - m];
    } else if (EP == MP_HR) {
        size_t o = ((size_t)(m * Bb + bz)) * Hh + n;
        splitH(g_hrh, g_hrl, o, acc * g_r[o]);
    } else if (EP == MP_H2) {
        g_h2[(size_t)m * Dd + n] = silu(acc + p.bias[n] + g_hx[(size_t)m * Dd + n]);
    } else if (EP == MP_RELU) {
        splitH(g_inh, g_inl, (size_t)m * II + n, fmaxf(acc + p.bias[n], 0.f));
    } else {
        p.out[(size_t)m * Dd + n] = acc + p.bias[n] + g_ol[(size_t)m * Dd + n];
    }
}

// CTA 256x128, warp 64x64 (4m x 2n), K-chunk 64, double-buffered, cp.async-fed.
// smem row = 128B; 16B-granular swizzle: unit' = unit ^ (row & 7).
// TERMS=3: Ah*Bh + Al*Bh + Ah*Bl (bf16).  TERMS=2: Ah*Bh + Al*Bh (fp16, B hi-only).
template<int EP, int TERMS, typename ET>
__global__ void __launch_bounds__(256, 1) k_mgemm(TG p) {
    constexpr int TM = 256, TN = 128;
    constexpr int ASZ = TM * 128;                 // 32768 per A matrix
    constexpr int BSZ = TN * 128;                 // 16384 per B matrix
    constexpr int NB = (TERMS == 3) ? 2 : 1;
    constexpr int STGB = 2 * ASZ + NB * BSZ;
    constexpr int KT = 64;

    extern __shared__ char sm[];
    const unsigned sb = smem_u32(sm);

    const int t = threadIdx.x, lane = t & 31, wid = t >> 5;
    const int wm = wid & 3, wn = wid >> 2;
    const int g = lane >> 2, tig = lane & 3;
    const int bz = blockIdx.z;
    const int m0 = blockIdx.y * TM, n0 = blockIdx.x * TN;
    const ET* Ahp = (const ET*)p.Ah + (size_t)bz * (size_t)p.sA;
    const ET* Alp = (const ET*)p.Al + (size_t)bz * (size_t)p.sA;
    const ET* Bhp = (const ET*)p.Bh + (size_t)bz * (size_t)p.sB;
    const ET* Blp = (TERMS == 3) ? ((const ET*)p.Bl + (size_t)bz * (size_t)p.sB) : nullptr;
    const int K = p.K;
    const int nst = K / KT;
    const int Nv = p.Nv;

    const int matq = lane >> 3, r8 = lane & 7;
    const int amq = matq >> 1, bmq = matq & 1;
    unsigned aBase[4]; int aswz[4];
#pragma unroll
    for (int mi = 0; mi < 4; mi++) {
        int arow = wm * 64 + mi * 16 + (matq & 1) * 8 + r8;
        aBase[mi] = sb + arow * 128;
        aswz[mi] = arow & 7;
    }
    unsigned bBase[2][2]; int bswz[2][2];
#pragma unroll
    for (int nh = 0; nh < 2; nh++)
#pragma unroll
        for (int njp = 0; njp < 2; njp++) {
            int brow = wn * 64 + nh * 32 + njp * 16 + (matq >> 1) * 8 + r8;
            bBase[nh][njp] = sb + 2 * ASZ + brow * 128;
            bswz[nh][njp] = brow & 7;
        }

    float acc[4][8][4];
#pragma unroll
    for (int i = 0; i < 4; i++)
#pragma unroll
        for (int j = 0; j < 8; j++)
#pragma unroll
            for (int r = 0; r < 4; r++) acc[i][j][r] = 0.f;

    auto CPA = [&](int k0, int buf) {
        unsigned ah = sb + buf * STGB, al = ah + ASZ;
#pragma unroll
        for (int j = 0; j < 8; j++) {
            int idx = t + 256 * j;
            int row = idx >> 3, q = idx & 7;
            unsigned off = row * 128 + ((q ^ (row & 7)) << 4);
            size_t go = (size_t)(m0 + row) * K + k0 + q * 8;
            cpa16(ah + off, Ahp + go);
            cpa16(al + off, Alp + go);
        }
    };
    auto CPB = [&](int k0, int buf) {
        unsigned bh = sb + buf * STGB + 2 * ASZ, bl = bh + BSZ;
#pragma unroll
        for (int j = 0; j < 4; j++) {
            int idx = t + 256 * j;
            int row = idx >> 3, q = idx & 7;
            int rn = n0 + row; if (rn >= Nv) rn = Nv - 1;
            unsigned off = row * 128 + ((q ^ (row & 7)) << 4);
            size_t go = (size_t)rn * K + k0 + q * 8;
            cpa16(bh + off, Bhp + go);
            if (TERMS == 3) cpa16(bl + off, Blp + go);
        }
    };

    auto COMPUTE = [&](int buf) {
        const unsigned off = buf * STGB;
#pragma unroll
        for (int kk = 0; kk < 4; kk++) {
            unsigned Ah[4][4], Al[4][4];
#pragma unroll
            for (int mi = 0; mi < 4; mi++) {
                unsigned ao = off + (((kk * 2 + amq) ^ aswz[mi]) << 4);
                ldsm4(Ah[mi], aBase[mi] + ao);
                ldsm4(Al[mi], aBase[mi] + ao + ASZ);
            }
#pragma unroll
            for (int nh = 0; nh < 2; nh++) {
                unsigned Bh4[2][4], Bl4[2][4];
#pragma unroll
                for (int njp = 0; njp < 2; njp++) {
                    unsigned bo = off + (((kk * 2 + bmq) ^ bswz[nh][njp]) << 4);
                    ldsm4(Bh4[njp], bBase[nh][njp] + bo);
                    if (TERMS == 3) ldsm4(Bl4[njp], bBase[nh][njp] + bo + BSZ);
                }
#pragma unroll
                for (int nj = 0; nj < 4; nj++) {
                    int njp = nj >> 1, hi = (nj & 1) * 2;
                    unsigned bfh[2] = { Bh4[njp][hi], Bh4[njp][hi + 1] };
#pragma unroll
                    for (int mi = 0; mi < 4; mi++) {
                        float* c = acc[mi][nh * 4 + nj];
                        MMA<ET>::run(c, Ah[mi], bfh);
                        MMA<ET>::run(c, Al[mi], bfh);
                        if (TERMS == 3) {
                            unsigned bfl[2] = { Bl4[njp][hi], Bl4[njp][hi + 1] };
                            MMA<ET>::run(c, Ah[mi], bfl);
                        }
                    }
                }
            }
        }
    };

    CPA(0, 0); CPB(0, 0); CP_COMMIT;
    CP_WAIT0;
    __syncthreads();

    for (int s = 0; s < nst; s++) {
        if (s + 1 < nst) { CPA((s + 1) * KT, (s + 1) & 1); CPB((s + 1) * KT, (s + 1) & 1); CP_COMMIT; }
        COMPUTE(s & 1);
        if (s + 1 < nst) CP_WAIT0;
        __syncthreads();
    }

#pragma unroll
    for (int mi = 0; mi < 4; mi++)
#pragma unroll
        for (int ni = 0; ni < 8; ni++) {
            int row0 = m0 + wm * 64 + mi * 16 + g;
            int col0 = n0 + wn * 64 + ni * 8 + 2 * tig;
            float* c = acc[mi][ni];
            if (col0 < Nv)     epiM<EP>(p, bz, row0,     col0,     c[0]);
            if (col0 + 1 < Nv) epiM<EP>(p, bz, row0,     col0 + 1, c[1]);
            if (col0 < Nv)     epiM<EP>(p, bz, row0 + 8, col0,     c[2]);
            if (col0 + 1 < Nv) epiM<EP>(p, bz, row0 + 8, col0 + 1, c[3]);
        }
}

// ---------------- launch ----------------
constexpr int SMM3 = 2 * (2 * 256 * 128 + 2 * 128 * 128);  // 196608
constexpr int SMM2 = 2 * (2 * 256 * 128 + 1 * 128 * 128);  // 163840
typedef __nv_bfloat16 BF;
typedef __half HF;

extern "C" void kernel_launch(void* const* d_in, const int* in_sizes, int n_in,
                              void* d_out, int out_size) {
    (void)in_sizes; (void)n_in; (void)out_size;
    const float* x    = (const float*)d_in[0];
    const float* ln_s = (const float*)d_in[1];
    const float* ln_b = (const float*)d_in[2];
    const float* v_w  = (const float*)d_in[3];
    const float* v_b  = (const float*)d_in[4];
    const float* mx_w = (const float*)d_in[5];
    const float* mx_b = (const float*)d_in[6];
    const float* h_w  = (const float*)d_in[7];
    const float* h_b  = (const float*)d_in[8];
    const float* gamma= (const float*)d_in[9];
    const float* beta = (const float*)d_in[10];
    const float* rel  = (const float*)d_in[11];
    const float* e_d  = (const float*)d_in[12];
    const float* e_a  = (const float*)d_in[13];
    const float* e_b  = (const float*)d_in[14];
    const float* e_g  = (const float*)d_in[15];
    const float* e_o  = (const float*)d_in[16];
    const float* f_s  = (const float*)d_in[17];
    const float* f_b  = (const float*)d_in[18];
    const float* w1   = (const float*)d_in[19];
    const float* b1   = (const float*)d_in[20];
    const float* w2   = (const float*)d_in[21];
    const float* b2   = (const float*)d_in[22];

    HF *p_xnh, *p_xnl, *p_sch, *p_scl, *p_hrh, *p_hrl, *p_olh, *p_oll, *p_inh, *p_inl;
    HF *p_vh, *p_wvh, *p_whh, *p_w1h, *p_w2h;
    BF *p_mxh, *p_mxl, *p_qh, *p_ql, *p_kh, *p_kl, *p_wmh, *p_wml;
    cudaGetSymbolAddress((void**)&p_xnh, g_xnh);
    cudaGetSymbolAddress((void**)&p_xnl, g_xnl);
    cudaGetSymbolAddress((void**)&p_sch, g_sch);
    cudaGetSymbolAddress((void**)&p_scl, g_scl);
    cudaGetSymbolAddress((void**)&p_hrh, g_hrh);
    cudaGetSymbolAddress((void**)&p_hrl, g_hrl);
    cudaGetSymbolAddress((void**)&p_olh, g_olh);
    cudaGetSymbolAddress((void**)&p_oll, g_oll);
    cudaGetSymbolAddress((void**)&p_inh, g_inh);
    cudaGetSymbolAddress((void**)&p_inl, g_inl);
    cudaGetSymbolAddress((void**)&p_vh,  g_vh);
    cudaGetSymbolAddress((void**)&p_wvh, g_wvh);
    cudaGetSymbolAddress((void**)&p_whh, g_whh);
    cudaGetSymbolAddress((void**)&p_w1h, g_w1h);
    cudaGetSymbolAddress((void**)&p_w2h, g_w2h);
    cudaGetSymbolAddress((void**)&p_mxh, g_mxh);
    cudaGetSymbolAddress((void**)&p_mxl, g_mxl);
    cudaGetSymbolAddress((void**)&p_qh,  g_qh);
    cudaGetSymbolAddress((void**)&p_ql,  g_ql);
    cudaGetSymbolAddress((void**)&p_kh,  g_kh);
    cudaGetSymbolAddress((void**)&p_kl,  g_kl);
    cudaGetSymbolAddress((void**)&p_wmh, g_wmh);
    cudaGetSymbolAddress((void**)&p_wml, g_wml);

    cudaFuncSetAttribute(k_mgemm<MP_V,    2, HF>, cudaFuncAttributeMaxDynamicSharedMemorySize, SMM2);
    cudaFuncSetAttribute(k_mgemm<MP_BASE, 3, BF>, cudaFuncAttributeMaxDynamicSharedMemorySize, SMM3);
    cudaFuncSetAttribute(k_mgemm<MP_SC,   3, BF>, cudaFuncAttributeMaxDynamicSharedMemorySize, SMM3);
    cudaFuncSetAttribute(k_mgemm<MP_HR,   2, HF>, cudaFuncAttributeMaxDynamicSharedMemorySize, SMM2);
    cudaFuncSetAttribute(k_mgemm<MP_H2,   2, HF>, cudaFuncAttributeMaxDynamicSharedMemorySize, SMM2);
    cudaFuncSetAttribute(k_mgemm<MP_RELU, 2, HF>, cudaFuncAttributeMaxDynamicSharedMemorySize, SMM2);
    cudaFuncSetAttribute(k_mgemm<MP_FIN,  2, HF>, cudaFuncAttributeMaxDynamicSharedMemorySize, SMM2);

    // weight prep
    k_wt<HF, false><<<dim3(Hh / 32, Dd / 32), 256>>>(v_w, p_wvh, nullptr, Dd, Hh);
    k_wt<BF, true ><<<dim3(NMX / 32, Dd / 32), 256>>>(mx_w, p_wmh, p_wml, Dd, NMX);
    k_wt<HF, false><<<dim3(Dd / 32, Hh / 32), 256>>>(h_w, p_whh, nullptr, Hh, Dd);
    k_wt<HF, false><<<dim3(II / 32, Dd / 32), 256>>>(w1, p_w1h, nullptr, Dd, II);
    k_wt<HF, false><<<dim3(Dd / 32, II / 32), 256>>>(w2, p_w2h, nullptr, II, Dd);

    k_ln1<<<SB, 256>>>(x, ln_s, ln_b);
    k_ema<<<(Bb * Dd) / 16, 256>>>(e_d, e_a, e_b, e_g, e_o);

    TG p;
    // v = silu(xn @ v_w + v_b) -> v^T fp16 (2-term)
    p = {p_xnh, p_xnl, p_wvh, nullptr, v_b, nullptr, nullptr, nullptr, Dd, Hh, 0, 0};
    k_mgemm<MP_V, 2, HF><<<dim3(Hh / 128, SB / 256, 1), 256, SMM2>>>(p);
    // base = mx @ mx_w + mx_b -> u,(q,k),r,hx  (3-term bf16)
    p = {p_mxh, p_mxl, p_wmh, p_wml, mx_b, gamma, beta, nullptr, Dd, NMX, 0, 0};
    k_mgemm<MP_BASE, 3, BF><<<dim3(NMX / 128, SB / 256, 1), 256, SMM3>>>(p);
    // scores = scaling * q @ k^T + relpos  (3-term bf16, batched)
    p = {p_qh, p_ql, p_kh, p_kl, nullptr, rel, nullptr, nullptr, Zz, Ss, (long long)Ss * Zz, (long long)Ss * Zz};
    k_mgemm<MP_SC, 3, BF><<<dim3(Ss / 128, Ss / 256, Bb), 256, SMM3>>>(p);
    k_softmax<<<Bb * Ss, 256>>>();
    // hr = (attn @ v) * r  (2-term fp16, batched, fused)
    p = {p_sch, p_scl, p_vh, nullptr, nullptr, nullptr, nullptr, nullptr, Ss, Hh, (long long)Ss * Ss, (long long)Hh * Ss};
    k_mgemm<MP_HR, 2, HF><<<dim3(Hh / 128, Ss / 256, Bb), 256, SMM2>>>(p);
    // h2 = silu(hx + hr @ h_w + h_b)  (2-term fp16)
    p = {p_hrh, p_hrl, p_whh, nullptr, h_b, nullptr, nullptr, nullptr, Hh, Dd, 0, 0};
    k_mgemm<MP_H2, 2, HF><<<dim3(Dd / 128, SB / 256, 1), 256, SMM2>>>(p);
    k_gateln<<<SB, 256>>>(f_s, f_b);
    // FFN  (2-term fp16)
    p = {p_olh, p_oll, p_w1h, nullptr, b1, nullptr, nullptr, nullptr, Dd, II, 0, 0};
    k_mgemm<MP_RELU, 2, HF><<<dim3(II / 128, SB / 256, 1), 256, SMM2>>>(p);
    p = {p_inh, p_inl, p_w2h, nullptr, b2, nullptr, nullptr, (float*)d_out, II, Dd, 0, 0};
    k_mgemm<MP_FIN, 2, HF><<<dim3(Dd / 128, SB / 256, 1), 256, SMM2>>>(p);
}

// round 13
// speedup vs baseline: 1.4955x; 1.2591x over previous
#include <cuda_runtime.h>
#include <cuda_bf16.h>
#include <cuda_fp16.h>
#include <math.h>

#define DEVFN __device__ __forceinline__
#define DG __device__ __align__(128)

constexpr int Bb = 8, Ss = 2048, Dd = 1024, Zz = 128, Nn = 16, Hh = 2048, II = 4096, MPc = 2048;
constexpr int SB = Ss * Bb;
constexpr int NMX = Dd + Zz + Hh + Dd;  // 4224
constexpr float EPS = 1e-3f;
constexpr float SCALING = 0.08838834764831843f;

// ---------------- scratch ----------------
DG float g_xn[(size_t)SB * Dd];
DG float g_u [(size_t)SB * Dd];
DG float g_hx[(size_t)SB * Dd];
DG float g_r [(size_t)SB * Hh];
DG float g_sc[(size_t)Bb * Ss * Ss];
DG float g_h2[(size_t)SB * Dd];
DG float g_ol[(size_t)SB * Dd];
// fp16 A operands (1-term GEMMs)
DG __half g_xnh[(size_t)SB * Dd];
DG __half g_sch[(size_t)Bb * Ss * Ss];
DG __half g_hrh[(size_t)SB * Hh];
DG __half g_olh[(size_t)SB * Dd];
DG __half g_inh[(size_t)SB * II];
// fp16 B operands (1-term GEMMs)
DG __half g_vh [(size_t)Bb * Hh * Ss];
DG __half g_wvh[(size_t)Hh * Dd];
DG __half g_whh[(size_t)Dd * Hh];
DG __half g_w1h[(size_t)II * Dd];
DG __half g_w2h[(size_t)Dd * II];
// bf16 split operands (3-term GEMMs: mx-proj, scores)
DG __nv_bfloat16 g_mxh[(size_t)SB * Dd],      g_mxl[(size_t)SB * Dd];
DG __nv_bfloat16 g_qh [(size_t)Bb * Ss * Zz], g_ql [(size_t)Bb * Ss * Zz];
DG __nv_bfloat16 g_kh [(size_t)Bb * Ss * Zz], g_kl [(size_t)Bb * Ss * Zz];
DG __nv_bfloat16 g_wmh[(size_t)NMX * Dd],     g_wml[(size_t)NMX * Dd];

// ---------------- helpers ----------------
DEVFN float sigm(float x) { return 1.f / (1.f + __expf(-x)); }
DEVFN float silu(float x) { return x / (1.f + __expf(-x)); }
DEVFN void splitB(__nv_bfloat16* oh, __nv_bfloat16* ol, size_t i, float v) {
    __nv_bfloat16 h = __float2bfloat16(v);
    oh[i] = h;
    ol[i] = __float2bfloat16(v - __bfloat162float(h));
}
DEVFN float warpSum(float v) {
#pragma unroll
    for (int o = 16; o; o >>= 1) v += __shfl_xor_sync(~0u, v, o);
    return v;
}
DEVFN float warpMax(float v) {
#pragma unroll
    for (int o = 16; o; o >>= 1) v = fmaxf(v, __shfl_xor_sync(~0u, v, o));
    return v;
}
DEVFN void blockSum2(float& a, float& b) {
    __shared__ float sa[8], sb_[8];
    float wa = warpSum(a), wb = warpSum(b);
    if ((threadIdx.x & 31) == 0) { sa[threadIdx.x >> 5] = wa; sb_[threadIdx.x >> 5] = wb; }
    __syncthreads();
    a = b = 0.f;
#pragma unroll
    for (int i = 0; i < 8; i++) { a += sa[i]; b += sb_[i]; }
    __syncthreads();
}
DEVFN float blockSum1(float v) {
    __shared__ float s[8];
    float w = warpSum(v);
    if ((threadIdx.x & 31) == 0) s[threadIdx.x >> 5] = w;
    __syncthreads();
    float r = 0.f;
#pragma unroll
    for (int i = 0; i < 8; i++) r += s[i];
    __syncthreads();
    return r;
}
DEVFN float blockMax1(float v) {
    __shared__ float s[8];
    float w = warpMax(v);
    if ((threadIdx.x & 31) == 0) s[threadIdx.x >> 5] = w;
    __syncthreads();
    float r = s[0];
#pragma unroll
    for (int i = 1; i < 8; i++) r = fmaxf(r, s[i]);
    __syncthreads();
    return r;
}

template<typename ET> struct MMA;
template<> struct MMA<__nv_bfloat16> {
    static DEVFN void run(float* c, const unsigned* a, const unsigned* b) {
        asm volatile(
            "mma.sync.aligned.m16n8k16.row.col.f32.bf16.bf16.f32 "
            "{%0,%1,%2,%3},{%4,%5,%6,%7},{%8,%9},{%0,%1,%2,%3};"
            : "+f"(c[0]), "+f"(c[1]), "+f"(c[2]), "+f"(c[3])
            : "r"(a[0]), "r"(a[1]), "r"(a[2]), "r"(a[3]), "r"(b[0]), "r"(b[1]));
    }
};
template<> struct MMA<__half> {
    static DEVFN void run(float* c, const unsigned* a, const unsigned* b) {
        asm volatile(
            "mma.sync.aligned.m16n8k16.row.col.f32.f16.f16.f32 "
            "{%0,%1,%2,%3},{%4,%5,%6,%7},{%8,%9},{%0,%1,%2,%3};"
            : "+f"(c[0]), "+f"(c[1]), "+f"(c[2]), "+f"(c[3])
            : "r"(a[0]), "r"(a[1]), "r"(a[2]), "r"(a[3]), "r"(b[0]), "r"(b[1]));
    }
};

DEVFN void ldsm4(unsigned* r, unsigned addr) {
    asm volatile("ldmatrix.sync.aligned.m8n8.x4.shared.b16 {%0,%1,%2,%3}, [%4];"
                 : "=r"(r[0]), "=r"(r[1]), "=r"(r[2]), "=r"(r[3]) : "r"(addr));
}
DEVFN void cpa16(unsigned dst, const void* src) {
    asm volatile("cp.async.cg.shared.global [%0], [%1], 16;" :: "r"(dst), "l"(src) : "memory");
}
#define CP_COMMIT asm volatile("cp.async.commit_group;" ::: "memory")
#define CP_WAIT0  asm volatile("cp.async.wait_group 0;" ::: "memory")
DEVFN unsigned smem_u32(const void* p) {
    unsigned a;
    asm("{ .reg .u64 t; cvta.to.shared.u64 t, %1; cvt.u32.u64 %0, t; }" : "=r"(a) : "l"(p));
    return a;
}

// ---------------- elementwise ----------------
__global__ __launch_bounds__(256) void k_ln1(const float* __restrict__ x,
                                             const float* __restrict__ sc,
                                             const float* __restrict__ bi) {
    int m = blockIdx.x, b = m / Ss, s = m % Ss, t = threadIdx.x;
    const float* xr = x + (size_t)m * Dd;
    float v[4], su = 0.f, sq = 0.f;
#pragma unroll
    for (int i = 0; i < 4; i++) { float f = xr[t + 256 * i]; v[i] = f; su += f; sq += f * f; }
    blockSum2(su, sq);
    float mu = su * (1.f / Dd), inv = rsqrtf(sq * (1.f / Dd) - mu * mu + EPS);
    size_t base = (size_t)(s * Bb + b) * Dd;
#pragma unroll
    for (int i = 0; i < 4; i++) {
        int d = t + 256 * i;
        float val = (v[i] - mu) * inv * sc[d] + bi[d];
        g_xn[base + d] = val;
        g_xnh[base + d] = __float2half_rn(val);
    }
}

__global__ __launch_bounds__(256) void k_ema(const float* __restrict__ de, const float* __restrict__ al,
                                             const float* __restrict__ be, const float* __restrict__ ga,
                                             const float* __restrict__ om) {
    int t = threadIdx.x, lane = t & 15;
    int P = blockIdx.x * 16 + (t >> 4), b = P / Dd, d = P % Dd;
    int pi = d * Nn + lane;
    float p = sigm(de[pi]);
    float q = 1.f - p * sigm(al[pi]);
    float coef = p * be[pi] * ga[pi] * 0.25f;
    float w = om[d];
    const float* xp = g_xn + (size_t)b * Dd + d;
    size_t obase = (size_t)b * Dd + d;
    float s = 0.f;
    for (int l = 0; l < Ss; l++) {
        float xv = xp[(size_t)l * (Bb * Dd)];
        s = fmaf(q, s, xv);
        float r = coef * s;
        r += __shfl_xor_sync(~0u, r, 1);
        r += __shfl_xor_sync(~0u, r, 2);
        r += __shfl_xor_sync(~0u, r, 4);
        r += __shfl_xor_sync(~0u, r, 8);
        if (lane == 0) {
            float val = silu(r + xv * w);
            splitB(g_mxh, g_mxl, obase + (size_t)l * (Bb * Dd), val);
        }
    }
}

__global__ __launch_bounds__(256) void k_softmax() {
    size_t rbase = (size_t)blockIdx.x * Ss;
    const float* rp = g_sc + rbase;
    int t = threadIdx.x;
    float v[8], mx = -1e30f;
#pragma unroll
    for (int i = 0; i < 8; i++) { v[i] = rp[t + 256 * i]; mx = fmaxf(mx, v[i]); }
    mx = blockMax1(mx);
    float su = 0.f;
#pragma unroll
    for (int i = 0; i < 8; i++) { v[i] = __expf(v[i] - mx); su += v[i]; }
    su = blockSum1(su);
    float inv = 1.f / su;
#pragma unroll
    for (int i = 0; i < 8; i++)
        g_sch[rbase + t + 256 * i] = __float2half_rn(v[i] * inv);
}

__global__ __launch_bounds__(256) void k_gateln(const float* __restrict__ sc,
                                                const float* __restrict__ bi) {
    int m = blockIdx.x, s = m >> 3, b = m & 7, t = threadIdx.x;
    size_t base = (size_t)m * Dd;
    float g[4], su = 0.f, sq = 0.f;
#pragma unroll
    for (int i = 0; i < 4; i++) {
        int d = t + 256 * i;
        float xn = g_xn[base + d];
        float val = xn + g_u[base + d] * (g_h2[base + d] - xn);
        g[i] = val; su += val; sq += val * val;
    }
    blockSum2(su, sq);
    float mu = su * (1.f / Dd), inv = rsqrtf(sq * (1.f / Dd) - mu * mu + EPS);
    size_t ob = ((size_t)b * Ss + s) * Dd;
#pragma unroll
    for (int i = 0; i < 4; i++) {
        int d = t + 256 * i;
        float val = (g[i] - mu) * inv * sc[d] + bi[d];
        g_ol[ob + d] = val;
        g_olh[ob + d] = __float2half_rn(val);
    }
}

// weight transpose+convert: LO=true -> hi/lo split, LO=false -> hi only
template<typename T, bool LO>
__global__ __launch_bounds__(256) void k_wt(const float* __restrict__ W,
                                            T* __restrict__ oh,
                                            T* __restrict__ ol, int K, int N) {
    __shared__ float tl[32][33];
    int n0 = blockIdx.x * 32, k0 = blockIdx.y * 32;
    int tx = threadIdx.x & 31, ty = threadIdx.x >> 5;
#pragma unroll
    for (int i = 0; i < 4; i++) tl[ty + i * 8][tx] = W[(size_t)(k0 + ty + i * 8) * N + n0 + tx];
    __syncthreads();
#pragma unroll
    for (int i = 0; i < 4; i++) {
        int ny = ty + i * 8;
        float v = tl[tx][ny];
        size_t o = (size_t)(n0 + ny) * K + k0 + tx;
        T h = (T)v;
        oh[o] = h;
        if (LO) ol[o] = (T)(v - (float)h);
    }
}

// ================= mma.sync GEMM (TM=256,TN=128, KT=64) =================
struct TG {
    const void* Ah; const void* Al;
    const void* Bh; const void* Bl;
    const float* bias; const float* aux; const float* aux2;
    float* out;
    int K, Nv;
    long long sA, sB;
};

enum { MP_V = 0, MP_BASE, MP_SC, MP_HR, MP_H2, MP_RELU, MP_FIN };

template<int EP>
DEVFN void epiM(const TG& p, int bz, int m, int n, float acc) {
    if (EP == MP_V) {
        float v = silu(acc + p.bias[n]);
        int s = m >> 3, b = m & 7;
        g_vh[((size_t)(b * Hh + n)) * Ss + s] = __float2half_rn(v);
    } else if (EP == MP_BASE) {
        float a = acc + p.bias[n];
        if (n < Dd) {
            g_u[(size_t)m * Dd + n] = sigm(a);
        } else if (n < Dd + Zz) {
            float z = silu(a); int zi = n - Dd;
            int s = m >> 3, b = m & 7;
            size_t o = ((size_t)(b * Ss + s)) * Zz + zi;
            splitB(g_qh, g_ql, o, z * p.aux[zi] + p.aux2[zi]);
            splitB(g_kh, g_kl, o, z * p.aux[Zz + zi] + p.aux2[Zz + zi]);
        } else if (n < Dd + Zz + Hh) {
            g_r[(size_t)m * Hh + (n - Dd - Zz)] = silu(a);
        } else {
            g_hx[(size_t)m * Dd + (n - Dd - Zz - Hh)] = a;
        }
    } else if (EP == MP_SC) {
        g_sc[((size_t)bz * Ss + m) * Ss + n] = acc * SCALING + p.aux[MPc - 1 + n - m];
    } else if (EP == MP_HR) {
        size_t o = ((size_t)(m * Bb + bz)) * Hh + n;
        g_hrh[o] = __float2half_rn(acc * g_r[o]);
    } else if (EP == MP_H2) {
        g_h2[(size_t)m * Dd + n] = silu(acc + p.bias[n] + g_hx[(size_t)m * Dd + n]);
    } else if (EP == MP_RELU) {
        g_inh[(size_t)m * II + n] = __float2half_rn(fmaxf(acc + p.bias[n], 0.f));
    } else {
        p.out[(size_t)m * Dd + n] = acc + p.bias[n] + g_ol[(size_t)m * Dd + n];
    }
}

// CTA 256x128, warp 64x64 (4m x 2n), K-chunk 64, double-buffered, cp.async-fed.
// smem row = 128B; 16B-granular swizzle: unit' = unit ^ (row & 7).
// TERMS=3: Ah*Bh + Al*Bh + Ah*Bl (bf16 split).  TERMS=1: Ah*Bh (fp16 plain).
template<int EP, int TERMS, typename ET>
__global__ void __launch_bounds__(256, 1) k_mgemm(TG p) {
    constexpr int TM = 256, TN = 128;
    constexpr int ASZ = TM * 128;                 // 32768 per A matrix
    constexpr int BSZ = TN * 128;                 // 16384 per B matrix
    constexpr int NA = (TERMS >= 2) ? 2 : 1;
    constexpr int NB = (TERMS == 3) ? 2 : 1;
    constexpr int STGB = NA * ASZ + NB * BSZ;
    constexpr int KT = 64;

    extern __shared__ char sm[];
    const unsigned sb = smem_u32(sm);

    const int t = threadIdx.x, lane = t & 31, wid = t >> 5;
    const int wm = wid & 3, wn = wid >> 2;
    const int g = lane >> 2, tig = lane & 3;
    const int bz = blockIdx.z;
    const int m0 = blockIdx.y * TM, n0 = blockIdx.x * TN;
    const ET* Ahp = (const ET*)p.Ah + (size_t)bz * (size_t)p.sA;
    const ET* Alp = (NA == 2) ? ((const ET*)p.Al + (size_t)bz * (size_t)p.sA) : nullptr;
    const ET* Bhp = (const ET*)p.Bh + (size_t)bz * (size_t)p.sB;
    const ET* Blp = (NB == 2) ? ((const ET*)p.Bl + (size_t)bz * (size_t)p.sB) : nullptr;
    const int K = p.K;
    const int nst = K / KT;
    const int Nv = p.Nv;

    const int matq = lane >> 3, r8 = lane & 7;
    const int amq = matq >> 1, bmq = matq & 1;
    unsigned aBase[4]; int aswz[4];
#pragma unroll
    for (int mi = 0; mi < 4; mi++) {
        int arow = wm * 64 + mi * 16 + (matq & 1) * 8 + r8;
        aBase[mi] = sb + arow * 128;
        aswz[mi] = arow & 7;
    }
    unsigned bBase[2][2]; int bswz[2][2];
#pragma unroll
    for (int nh = 0; nh < 2; nh++)
#pragma unroll
        for (int njp = 0; njp < 2; njp++) {
            int brow = wn * 64 + nh * 32 + njp * 16 + (matq >> 1) * 8 + r8;
            bBase[nh][njp] = sb + NA * ASZ + brow * 128;
            bswz[nh][njp] = brow & 7;
        }

    float acc[4][8][4];
#pragma unroll
    for (int i = 0; i < 4; i++)
#pragma unroll
        for (int j = 0; j < 8; j++)
#pragma unroll
            for (int r = 0; r < 4; r++) acc[i][j][r] = 0.f;

    auto CPA = [&](int k0, int buf) {
        unsigned ah = sb + buf * STGB, al = ah + ASZ;
#pragma unroll
        for (int j = 0; j < 8; j++) {
            int idx = t + 256 * j;
            int row = idx >> 3, q = idx & 7;
            unsigned off = row * 128 + ((q ^ (row & 7)) << 4);
            size_t go = (size_t)(m0 + row) * K + k0 + q * 8;
            cpa16(ah + off, Ahp + go);
            if (NA == 2) cpa16(al + off, Alp + go);
        }
    };
    auto CPB = [&](int k0, int buf) {
        unsigned bh = sb + buf * STGB + NA * ASZ, bl = bh + BSZ;
#pragma unroll
        for (int j = 0; j < 4; j++) {
            int idx = t + 256 * j;
            int row = idx >> 3, q = idx & 7;
            int rn = n0 + row; if (rn >= Nv) rn = Nv - 1;
            unsigned off = row * 128 + ((q ^ (row & 7)) << 4);
            size_t go = (size_t)rn * K + k0 + q * 8;
            cpa16(bh + off, Bhp + go);
            if (NB == 2) cpa16(bl + off, Blp + go);
        }
    };

    auto COMPUTE = [&](int buf) {
        const unsigned off = buf * STGB;
#pragma unroll
        for (int kk = 0; kk < 4; kk++) {
            unsigned Ah[4][4], Al[4][4];
#pragma unroll
            for (int mi = 0; mi < 4; mi++) {
                unsigned ao = off + (((kk * 2 + amq) ^ aswz[mi]) << 4);
                ldsm4(Ah[mi], aBase[mi] + ao);
                if (NA == 2) ldsm4(Al[mi], aBase[mi] + ao + ASZ);
            }
#pragma unroll
            for (int nh = 0; nh < 2; nh++) {
                unsigned Bh4[2][4], Bl4[2][4];
#pragma unroll
                for (int njp = 0; njp < 2; njp++) {
                    unsigned bo = off + (((kk * 2 + bmq) ^ bswz[nh][njp]) << 4);
                    ldsm4(Bh4[njp], bBase[nh][njp] + bo);
                    if (NB == 2) ldsm4(Bl4[njp], bBase[nh][njp] + bo + BSZ);
                }
#pragma unroll
                for (int nj = 0; nj < 4; nj++) {
                    int njp = nj >> 1, hi = (nj & 1) * 2;
                    unsigned bfh[2] = { Bh4[njp][hi], Bh4[njp][hi + 1] };
#pragma unroll
                    for (int mi = 0; mi < 4; mi++) {
                        float* c = acc[mi][nh * 4 + nj];
                        MMA<ET>::run(c, Ah[mi], bfh);
                        if (NA == 2) MMA<ET>::run(c, Al[mi], bfh);
                        if (NB == 2) {
                            unsigned bfl[2] = { Bl4[njp][hi], Bl4[njp][hi + 1] };
                            MMA<ET>::run(c, Ah[mi], bfl);
                        }
                    }
                }
            }
        }
    };

    CPA(0, 0); CPB(0, 0); CP_COMMIT;
    CP_WAIT0;
    __syncthreads();

    for (int s = 0; s < nst; s++) {
        if (s + 1 < nst) { CPA((s + 1) * KT, (s + 1) & 1); CPB((s + 1) * KT, (s + 1) & 1); CP_COMMIT; }
        COMPUTE(s & 1);
        if (s + 1 < nst) CP_WAIT0;
        __syncthreads();
    }

#pragma unroll
    for (int mi = 0; mi < 4; mi++)
#pragma unroll
        for (int ni = 0; ni < 8; ni++) {
            int row0 = m0 + wm * 64 + mi * 16 + g;
            int col0 = n0 + wn * 64 + ni * 8 + 2 * tig;
            float* c = acc[mi][ni];
            if (col0 < Nv)     epiM<EP>(p, bz, row0,     col0,     c[0]);
            if (col0 + 1 < Nv) epiM<EP>(p, bz, row0,     col0 + 1, c[1]);
            if (col0 < Nv)     epiM<EP>(p, bz, row0 + 8, col0,     c[2]);
            if (col0 + 1 < Nv) epiM<EP>(p, bz, row0 + 8, col0 + 1, c[3]);
        }
}

// ---------------- launch ----------------
constexpr int SMM3 = 2 * (2 * 256 * 128 + 2 * 128 * 128);  // 196608
constexpr int SMM1 = 2 * (1 * 256 * 128 + 1 * 128 * 128);  // 98304
typedef __nv_bfloat16 BF;
typedef __half HF;

extern "C" void kernel_launch(void* const* d_in, const int* in_sizes, int n_in,
                              void* d_out, int out_size) {
    (void)in_sizes; (void)n_in; (void)out_size;
    const float* x    = (const float*)d_in[0];
    const float* ln_s = (const float*)d_in[1];
    const float* ln_b = (const float*)d_in[2];
    const float* v_w  = (const float*)d_in[3];
    const float* v_b  = (const float*)d_in[4];
    const float* mx_w = (const float*)d_in[5];
    const float* mx_b = (const float*)d_in[6];
    const float* h_w  = (const float*)d_in[7];
    const float* h_b  = (const float*)d_in[8];
    const float* gamma= (const float*)d_in[9];
    const float* beta = (const float*)d_in[10];
    const float* rel  = (const float*)d_in[11];
    const float* e_d  = (const float*)d_in[12];
    const float* e_a  = (const float*)d_in[13];
    const float* e_b  = (const float*)d_in[14];
    const float* e_g  = (const float*)d_in[15];
    const float* e_o  = (const float*)d_in[16];
    const float* f_s  = (const float*)d_in[17];
    const float* f_b  = (const float*)d_in[18];
    const float* w1   = (const float*)d_in[19];
    const float* b1   = (const float*)d_in[20];
    const float* w2   = (const float*)d_in[21];
    const float* b2   = (const float*)d_in[22];

    HF *p_xnh, *p_sch, *p_hrh, *p_olh, *p_inh;
    HF *p_vh, *p_wvh, *p_whh, *p_w1h, *p_w2h;
    BF *p_mxh, *p_mxl, *p_qh, *p_ql, *p_kh, *p_kl, *p_wmh, *p_wml;
    cudaGetSymbolAddress((void**)&p_xnh, g_xnh);
    cudaGetSymbolAddress((void**)&p_sch, g_sch);
    cudaGetSymbolAddress((void**)&p_hrh, g_hrh);
    cudaGetSymbolAddress((void**)&p_olh, g_olh);
    cudaGetSymbolAddress((void**)&p_inh, g_inh);
    cudaGetSymbolAddress((void**)&p_vh,  g_vh);
    cudaGetSymbolAddress((void**)&p_wvh, g_wvh);
    cudaGetSymbolAddress((void**)&p_whh, g_whh);
    cudaGetSymbolAddress((void**)&p_w1h, g_w1h);
    cudaGetSymbolAddress((void**)&p_w2h, g_w2h);
    cudaGetSymbolAddress((void**)&p_mxh, g_mxh);
    cudaGetSymbolAddress((void**)&p_mxl, g_mxl);
    cudaGetSymbolAddress((void**)&p_qh,  g_qh);
    cudaGetSymbolAddress((void**)&p_ql,  g_ql);
    cudaGetSymbolAddress((void**)&p_kh,  g_kh);
    cudaGetSymbolAddress((void**)&p_kl,  g_kl);
    cudaGetSymbolAddress((void**)&p_wmh, g_wmh);
    cudaGetSymbolAddress((void**)&p_wml, g_wml);

    cudaFuncSetAttribute(k_mgemm<MP_V,    1, HF>, cudaFuncAttributeMaxDynamicSharedMemorySize, SMM1);
    cudaFuncSetAttribute(k_mgemm<MP_BASE, 3, BF>, cudaFuncAttributeMaxDynamicSharedMemorySize, SMM3);
    cudaFuncSetAttribute(k_mgemm<MP_SC,   3, BF>, cudaFuncAttributeMaxDynamicSharedMemorySize, SMM3);
    cudaFuncSetAttribute(k_mgemm<MP_HR,   1, HF>, cudaFuncAttributeMaxDynamicSharedMemorySize, SMM1);
    cudaFuncSetAttribute(k_mgemm<MP_H2,   1, HF>, cudaFuncAttributeMaxDynamicSharedMemorySize, SMM1);
    cudaFuncSetAttribute(k_mgemm<MP_RELU, 1, HF>, cudaFuncAttributeMaxDynamicSharedMemorySize, SMM1);
    cudaFuncSetAttribute(k_mgemm<MP_FIN,  1, HF>, cudaFuncAttributeMaxDynamicSharedMemorySize, SMM1);

    // weight prep
    k_wt<HF, false><<<dim3(Hh / 32, Dd / 32), 256>>>(v_w, p_wvh, nullptr, Dd, Hh);
    k_wt<BF, true ><<<dim3(NMX / 32, Dd / 32), 256>>>(mx_w, p_wmh, p_wml, Dd, NMX);
    k_wt<HF, false><<<dim3(Dd / 32, Hh / 32), 256>>>(h_w, p_whh, nullptr, Hh, Dd);
    k_wt<HF, false><<<dim3(II / 32, Dd / 32), 256>>>(w1, p_w1h, nullptr, Dd, II);
    k_wt<HF, false><<<dim3(Dd / 32, II / 32), 256>>>(w2, p_w2h, nullptr, II, Dd);

    k_ln1<<<SB, 256>>>(x, ln_s, ln_b);
    k_ema<<<(Bb * Dd) / 16, 256>>>(e_d, e_a, e_b, e_g, e_o);

    TG p;
    // v = silu(xn @ v_w + v_b) -> v^T fp16  (1-term)
    p = {p_xnh, nullptr, p_wvh, nullptr, v_b, nullptr, nullptr, nullptr, Dd, Hh, 0, 0};
    k_mgemm<MP_V, 1, HF><<<dim3(Hh / 128, SB / 256, 1), 256, SMM1>>>(p);
    // base = mx @ mx_w + mx_b -> u,(q,k),r,hx  (3-term bf16)
    p = {p_mxh, p_mxl, p_wmh, p_wml, mx_b, gamma, beta, nullptr, Dd, NMX, 0, 0};
    k_mgemm<MP_BASE, 3, BF><<<dim3(NMX / 128, SB / 256, 1), 256, SMM3>>>(p);
    // scores = scaling * q @ k^T + relpos  (3-term bf16, batched)
    p = {p_qh, p_ql, p_kh, p_kl, nullptr, rel, nullptr, nullptr, Zz, Ss, (long long)Ss * Zz, (long long)Ss * Zz};
    k_mgemm<MP_SC, 3, BF><<<dim3(Ss / 128, Ss / 256, Bb), 256, SMM3>>>(p);
    k_softmax<<<Bb * Ss, 256>>>();
    // hr = (attn @ v) * r  (1-term fp16, batched, fused)
    p = {p_sch, nullptr, p_vh, nullptr, nullptr, nullptr, nullptr, nullptr, Ss, Hh, (long long)Ss * Ss, (long long)Hh * Ss};
    k_mgemm<MP_HR, 1, HF><<<dim3(Hh / 128, Ss / 256, Bb), 256, SMM1>>>(p);
    // h2 = silu(hx + hr @ h_w + h_b)  (1-term fp16)
    p = {p_hrh, nullptr, p_whh, nullptr, h_b, nullptr, nullptr, nullptr, Hh, Dd, 0, 0};
    k_mgemm<MP_H2, 1, HF><<<dim3(Dd / 128, SB / 256, 1), 256, SMM1>>>(p);
    k_gateln<<<SB, 256>>>(f_s, f_b);
    // FFN  (1-term fp16)
    p = {p_olh, nullptr, p_w1h, nullptr, b1, nullptr, nullptr, nullptr, Dd, II, 0, 0};
    k_mgemm<MP_RELU, 1, HF><<<dim3(II / 128, SB / 256, 1), 256, SMM1>>>(p);
    p = {p_inh, nullptr, p_w2h, nullptr, b2, nullptr, nullptr, (float*)d_out, II, Dd, 0, 0};
    k_mgemm<MP_FIN, 1, HF><<<dim3(Dd / 128, SB / 256, 1), 256, SMM1>>>(p);
}

// round 14
// speedup vs baseline: 1.5760x; 1.0538x over previous
#include <cuda_runtime.h>
#include <cuda_bf16.h>
#include <cuda_fp16.h>
#include <math.h>

#define DEVFN __device__ __forceinline__
#define DG __device__ __align__(128)

constexpr int Bb = 8, Ss = 2048, Dd = 1024, Zz = 128, Nn = 16, Hh = 2048, II = 4096, MPc = 2048;
constexpr int SB = Ss * Bb;
constexpr int NMX = Dd + Zz + Hh + Dd;  // 4224
constexpr float EPS = 1e-3f;
constexpr float SCALING = 0.08838834764831843f;

// ---------------- scratch ----------------
DG float g_xn[(size_t)SB * Dd];
DG float g_u [(size_t)SB * Dd];
DG float g_hx[(size_t)SB * Dd];
DG float g_r [(size_t)SB * Hh];
DG float g_sc[(size_t)Bb * Ss * Ss];
DG float g_h2[(size_t)SB * Dd];
DG float g_ol[(size_t)SB * Dd];
// fp16 A operands
DG __half g_xnh[(size_t)SB * Dd];
DG __half g_sch[(size_t)Bb * Ss * Ss];
DG __half g_hrh[(size_t)SB * Hh];
DG __half g_olh[(size_t)SB * Dd];
DG __half g_inh[(size_t)SB * II];
DG __half g_mxh[(size_t)SB * Dd], g_mxl[(size_t)SB * Dd];   // 2-term fp16 A
// fp16 B operands
DG __half g_vh [(size_t)Bb * Hh * Ss];
DG __half g_wvh[(size_t)Hh * Dd];
DG __half g_whh[(size_t)Dd * Hh];
DG __half g_w1h[(size_t)II * Dd];
DG __half g_w2h[(size_t)Dd * II];
DG __half g_wmh[(size_t)NMX * Dd];                          // fp16 hi-only
// bf16 split operands (3-term scores GEMM)
DG __nv_bfloat16 g_qh[(size_t)Bb * Ss * Zz], g_ql[(size_t)Bb * Ss * Zz];
DG __nv_bfloat16 g_kh[(size_t)Bb * Ss * Zz], g_kl[(size_t)Bb * Ss * Zz];

// ---------------- helpers ----------------
DEVFN float sigm(float x) { return 1.f / (1.f + __expf(-x)); }
DEVFN float silu(float x) { return x / (1.f + __expf(-x)); }
DEVFN void splitB(__nv_bfloat16* oh, __nv_bfloat16* ol, size_t i, float v) {
    __nv_bfloat16 h = __float2bfloat16(v);
    oh[i] = h;
    ol[i] = __float2bfloat16(v - __bfloat162float(h));
}
DEVFN void splitH(__half* oh, __half* ol, size_t i, float v) {
    __half h = __float2half_rn(v);
    oh[i] = h;
    ol[i] = __float2half_rn(v - __half2float(h));
}
DEVFN float warpSum(float v) {
#pragma unroll
    for (int o = 16; o; o >>= 1) v += __shfl_xor_sync(~0u, v, o);
    return v;
}
DEVFN float warpMax(float v) {
#pragma unroll
    for (int o = 16; o; o >>= 1) v = fmaxf(v, __shfl_xor_sync(~0u, v, o));
    return v;
}
DEVFN void blockSum2(float& a, float& b) {
    __shared__ float sa[8], sb_[8];
    float wa = warpSum(a), wb = warpSum(b);
    if ((threadIdx.x & 31) == 0) { sa[threadIdx.x >> 5] = wa; sb_[threadIdx.x >> 5] = wb; }
    __syncthreads();
    a = b = 0.f;
#pragma unroll
    for (int i = 0; i < 8; i++) { a += sa[i]; b += sb_[i]; }
    __syncthreads();
}
DEVFN float blockSum1(float v) {
    __shared__ float s[8];
    float w = warpSum(v);
    if ((threadIdx.x & 31) == 0) s[threadIdx.x >> 5] = w;
    __syncthreads();
    float r = 0.f;
#pragma unroll
    for (int i = 0; i < 8; i++) r += s[i];
    __syncthreads();
    return r;
}
DEVFN float blockMax1(float v) {
    __shared__ float s[8];
    float w = warpMax(v);
    if ((threadIdx.x & 31) == 0) s[threadIdx.x >> 5] = w;
    __syncthreads();
    float r = s[0];
#pragma unroll
    for (int i = 1; i < 8; i++) r = fmaxf(r, s[i]);
    __syncthreads();
    return r;
}

template<typename ET> struct MMA;
template<> struct MMA<__nv_bfloat16> {
    static DEVFN void run(float* c, const unsigned* a, const unsigned* b) {
        asm volatile(
            "mma.sync.aligned.m16n8k16.row.col.f32.bf16.bf16.f32 "
            "{%0,%1,%2,%3},{%4,%5,%6,%7},{%8,%9},{%0,%1,%2,%3};"
            : "+f"(c[0]), "+f"(c[1]), "+f"(c[2]), "+f"(c[3])
            : "r"(a[0]), "r"(a[1]), "r"(a[2]), "r"(a[3]), "r"(b[0]), "r"(b[1]));
    }
};
template<> struct MMA<__half> {
    static DEVFN void run(float* c, const unsigned* a, const unsigned* b) {
        asm volatile(
            "mma.sync.aligned.m16n8k16.row.col.f32.f16.f16.f32 "
            "{%0,%1,%2,%3},{%4,%5,%6,%7},{%8,%9},{%0,%1,%2,%3};"
            : "+f"(c[0]), "+f"(c[1]), "+f"(c[2]), "+f"(c[3])
            : "r"(a[0]), "r"(a[1]), "r"(a[2]), "r"(a[3]), "r"(b[0]), "r"(b[1]));
    }
};

DEVFN void ldsm4(unsigned* r, unsigned addr) {
    asm volatile("ldmatrix.sync.aligned.m8n8.x4.shared.b16 {%0,%1,%2,%3}, [%4];"
                 : "=r"(r[0]), "=r"(r[1]), "=r"(r[2]), "=r"(r[3]) : "r"(addr));
}
DEVFN void cpa16(unsigned dst, const void* src) {
    asm volatile("cp.async.cg.shared.global [%0], [%1], 16;" :: "r"(dst), "l"(src) : "memory");
}
#define CP_COMMIT asm volatile("cp.async.commit_group;" ::: "memory")
#define CP_WAIT0  asm volatile("cp.async.wait_group 0;" ::: "memory")
DEVFN unsigned smem_u32(const void* p) {
    unsigned a;
    asm("{ .reg .u64 t; cvta.to.shared.u64 t, %1; cvt.u32.u64 %0, t; }" : "=r"(a) : "l"(p));
    return a;
}

// ---------------- elementwise ----------------
__global__ __launch_bounds__(256) void k_ln1(const float* __restrict__ x,
                                             const float* __restrict__ sc,
                                             const float* __restrict__ bi) {
    int m = blockIdx.x, b = m / Ss, s = m % Ss, t = threadIdx.x;
    const float* xr = x + (size_t)m * Dd;
    float v[4], su = 0.f, sq = 0.f;
#pragma unroll
    for (int i = 0; i < 4; i++) { float f = xr[t + 256 * i]; v[i] = f; su += f; sq += f * f; }
    blockSum2(su, sq);
    float mu = su * (1.f / Dd), inv = rsqrtf(sq * (1.f / Dd) - mu * mu + EPS);
    size_t base = (size_t)(s * Bb + b) * Dd;
#pragma unroll
    for (int i = 0; i < 4; i++) {
        int d = t + 256 * i;
        float val = (v[i] - mu) * inv * sc[d] + bi[d];
        g_xn[base + d] = val;
        g_xnh[base + d] = __float2half_rn(val);
    }
}

__global__ __launch_bounds__(256) void k_ema(const float* __restrict__ de, const float* __restrict__ al,
                                             const float* __restrict__ be, const float* __restrict__ ga,
                                             const float* __restrict__ om) {
    int t = threadIdx.x, lane = t & 15;
    int P = blockIdx.x * 16 + (t >> 4), b = P / Dd, d = P % Dd;
    int pi = d * Nn + lane;
    float p = sigm(de[pi]);
    float q = 1.f - p * sigm(al[pi]);
    float coef = p * be[pi] * ga[pi] * 0.25f;
    float w = om[d];
    const float* xp = g_xn + (size_t)b * Dd + d;
    size_t obase = (size_t)b * Dd + d;
    float s = 0.f;
    for (int l = 0; l < Ss; l++) {
        float xv = xp[(size_t)l * (Bb * Dd)];
        s = fmaf(q, s, xv);
        float r = coef * s;
        r += __shfl_xor_sync(~0u, r, 1);
        r += __shfl_xor_sync(~0u, r, 2);
        r += __shfl_xor_sync(~0u, r, 4);
        r += __shfl_xor_sync(~0u, r, 8);
        if (lane == 0) {
            float val = silu(r + xv * w);
            splitH(g_mxh, g_mxl, obase + (size_t)l * (Bb * Dd), val);
        }
    }
}

__global__ __launch_bounds__(256) void k_softmax() {
    size_t rbase = (size_t)blockIdx.x * Ss;
    const float* rp = g_sc + rbase;
    int t = threadIdx.x;
    float v[8], mx = -1e30f;
#pragma unroll
    for (int i = 0; i < 8; i++) { v[i] = rp[t + 256 * i]; mx = fmaxf(mx, v[i]); }
    mx = blockMax1(mx);
    float su = 0.f;
#pragma unroll
    for (int i = 0; i < 8; i++) { v[i] = __expf(v[i] - mx); su += v[i]; }
    su = blockSum1(su);
    float inv = 1.f / su;
#pragma unroll
    for (int i = 0; i < 8; i++)
        g_sch[rbase + t + 256 * i] = __float2half_rn(v[i] * inv);
}

__global__ __launch_bounds__(256) void k_gateln(const float* __restrict__ sc,
                                                const float* __restrict__ bi) {
    int m = blockIdx.x, s = m >> 3, b = m & 7, t = threadIdx.x;
    size_t base = (size_t)m * Dd;
    float g[4], su = 0.f, sq = 0.f;
#pragma unroll
    for (int i = 0; i < 4; i++) {
        int d = t + 256 * i;
        float xn = g_xn[base + d];
        float val = xn + g_u[base + d] * (g_h2[base + d] - xn);
        g[i] = val; su += val; sq += val * val;
    }
    blockSum2(su, sq);
    float mu = su * (1.f / Dd), inv = rsqrtf(sq * (1.f / Dd) - mu * mu + EPS);
    size_t ob = ((size_t)b * Ss + s) * Dd;
#pragma unroll
    for (int i = 0; i < 4; i++) {
        int d = t + 256 * i;
        float val = (g[i] - mu) * inv * sc[d] + bi[d];
        g_ol[ob + d] = val;
        g_olh[ob + d] = __float2half_rn(val);
    }
}

template<typename T, bool LO>
__global__ __launch_bounds__(256) void k_wt(const float* __restrict__ W,
                                            T* __restrict__ oh,
                                            T* __restrict__ ol, int K, int N) {
    __shared__ float tl[32][33];
    int n0 = blockIdx.x * 32, k0 = blockIdx.y * 32;
    int tx = threadIdx.x & 31, ty = threadIdx.x >> 5;
#pragma unroll
    for (int i = 0; i < 4; i++) tl[ty + i * 8][tx] = W[(size_t)(k0 + ty + i * 8) * N + n0 + tx];
    __syncthreads();
#pragma unroll
    for (int i = 0; i < 4; i++) {
        int ny = ty + i * 8;
        float v = tl[tx][ny];
        size_t o = (size_t)(n0 + ny) * K + k0 + tx;
        T h = (T)v;
        oh[o] = h;
        if (LO) ol[o] = (T)(v - (float)h);
    }
}

// ================= mma.sync GEMM (TM=256,TN=128, KT=64) =================
struct TG {
    const void* Ah; const void* Al;
    const void* Bh; const void* Bl;
    const float* bias; const float* aux; const float* aux2;
    float* out;
    int K, Nv;
    long long sA, sB;
};

enum { MP_V = 0, MP_BASE, MP_SC, MP_HR, MP_H2, MP_RELU, MP_FIN };

template<int EP>
DEVFN void epiM(const TG& p, int bz, int m, int n, float acc) {
    if (EP == MP_V) {
        float v = silu(acc + p.bias[n]);
        int s = m >> 3, b = m & 7;
        g_vh[((size_t)(b * Hh + n)) * Ss + s] = __float2half_rn(v);
    } else if (EP == MP_BASE) {
        float a = acc + p.bias[n];
        if (n < Dd) {
            g_u[(size_t)m * Dd + n] = sigm(a);
        } else if (n < Dd + Zz) {
            float z = silu(a); int zi = n - Dd;
            int s = m >> 3, b = m & 7;
            size_t o = ((size_t)(b * Ss + s)) * Zz + zi;
            splitB(g_qh, g_ql, o, z * p.aux[zi] + p.aux2[zi]);
            splitB(g_kh, g_kl, o, z * p.aux[Zz + zi] + p.aux2[Zz + zi]);
        } else if (n < Dd + Zz + Hh) {
            g_r[(size_t)m * Hh + (n - Dd - Zz)] = silu(a);
        } else {
            g_hx[(size_t)m * Dd + (n - Dd - Zz - Hh)] = a;
        }
    } else if (EP == MP_SC) {
        g_sc[((size_t)bz * Ss + m) * Ss + n] = acc * SCALING + p.aux[MPc - 1 + n - m];
    } else if (EP == MP_HR) {
        size_t o = ((size_t)(m * Bb + bz)) * Hh + n;
        g_hrh[o] = __float2half_rn(acc * g_r[o]);
    } else if (EP == MP_H2) {
        g_h2[(size_t)m * Dd + n] = silu(acc + p.bias[n] + g_hx[(size_t)m * Dd + n]);
    } else if (EP == MP_RELU) {
        g_inh[(size_t)m * II + n] = __float2half_rn(fmaxf(acc + p.bias[n], 0.f));
    } else {
        p.out[(size_t)m * Dd + n] = acc + p.bias[n] + g_ol[(size_t)m * Dd + n];
    }
}

// CTA 256x128, warp 64x64 (4m x 2n), K-chunk 64, double-buffered, cp.async-fed.
// TERMS=3: Ah*Bh+Al*Bh+Ah*Bl (bf16). TERMS=2: Ah*Bh+Al*Bh (fp16). TERMS=1: Ah*Bh (fp16).
template<int EP, int TERMS, typename ET>
__global__ void __launch_bounds__(256, 1) k_mgemm(TG p) {
    constexpr int TM = 256, TN = 128;
    constexpr int ASZ = TM * 128;
    constexpr int BSZ = TN * 128;
    constexpr int NA = (TERMS >= 2) ? 2 : 1;
    constexpr int NB = (TERMS == 3) ? 2 : 1;
    constexpr int STGB = NA * ASZ + NB * BSZ;
    constexpr int KT = 64;

    extern __shared__ char sm[];
    const unsigned sb = smem_u32(sm);

    const int t = threadIdx.x, lane = t & 31, wid = t >> 5;
    const int wm = wid & 3, wn = wid >> 2;
    const int g = lane >> 2, tig = lane & 3;
    const int bz = blockIdx.z;
    const int m0 = blockIdx.y * TM, n0 = blockIdx.x * TN;
    const ET* Ahp = (const ET*)p.Ah + (size_t)bz * (size_t)p.sA;
    const ET* Alp = (NA == 2) ? ((const ET*)p.Al + (size_t)bz * (size_t)p.sA) : nullptr;
    const ET* Bhp = (const ET*)p.Bh + (size_t)bz * (size_t)p.sB;
    const ET* Blp = (NB == 2) ? ((const ET*)p.Bl + (size_t)bz * (size_t)p.sB) : nullptr;
    const int K = p.K;
    const int nst = K / KT;
    const int Nv = p.Nv;

    const int matq = lane >> 3, r8 = lane & 7;
    const int amq = matq >> 1, bmq = matq & 1;
    unsigned aBase[4]; int aswz[4];
#pragma unroll
    for (int mi = 0; mi < 4; mi++) {
        int arow = wm * 64 + mi * 16 + (matq & 1) * 8 + r8;
        aBase[mi] = sb + arow * 128;
        aswz[mi] = arow & 7;
    }
    unsigned bBase[2][2]; int bswz[2][2];
#pragma unroll
    for (int nh = 0; nh < 2; nh++)
#pragma unroll
        for (int njp = 0; njp < 2; njp++) {
            int brow = wn * 64 + nh * 32 + njp * 16 + (matq >> 1) * 8 + r8;
            bBase[nh][njp] = sb + NA * ASZ + brow * 128;
            bswz[nh][njp] = brow & 7;
        }

    float acc[4][8][4];
#pragma unroll
    for (int i = 0; i < 4; i++)
#pragma unroll
        for (int j = 0; j < 8; j++)
#pragma unroll
            for (int r = 0; r < 4; r++) acc[i][j][r] = 0.f;

    auto CPA = [&](int k0, int buf) {
        unsigned ah = sb + buf * STGB, al = ah + ASZ;
#pragma unroll
        for (int j = 0; j < 8; j++) {
            int idx = t + 256 * j;
            int row = idx >> 3, q = idx & 7;
            unsigned off = row * 128 + ((q ^ (row & 7)) << 4);
            size_t go = (size_t)(m0 + row) * K + k0 + q * 8;
            cpa16(ah + off, Ahp + go);
            if (NA == 2) cpa16(al + off, Alp + go);
        }
    };
    auto CPB = [&](int k0, int buf) {
        unsigned bh = sb + buf * STGB + NA * ASZ, bl = bh + BSZ;
#pragma unroll
        for (int j = 0; j < 4; j++) {
            int idx = t + 256 * j;
            int row = idx >> 3, q = idx & 7;
            int rn = n0 + row; if (rn >= Nv) rn = Nv - 1;
            unsigned off = row * 128 + ((q ^ (row & 7)) << 4);
            size_t go = (size_t)rn * K + k0 + q * 8;
            cpa16(bh + off, Bhp + go);
            if (NB == 2) cpa16(bl + off, Blp + go);
        }
    };

    auto COMPUTE = [&](int buf) {
        const unsigned off = buf * STGB;
#pragma unroll
        for (int kk = 0; kk < 4; kk++) {
            unsigned Ah[4][4], Al[4][4];
#pragma unroll
            for (int mi = 0; mi < 4; mi++) {
                unsigned ao = off + (((kk * 2 + amq) ^ aswz[mi]) << 4);
                ldsm4(Ah[mi], aBase[mi] + ao);
                if (NA == 2) ldsm4(Al[mi], aBase[mi] + ao + ASZ);
            }
#pragma unroll
            for (int nh = 0; nh < 2; nh++) {
                unsigned Bh4[2][4], Bl4[2][4];
#pragma unroll
                for (int njp = 0; njp < 2; njp++) {
                    unsigned bo = off + (((kk * 2 + bmq) ^ bswz[nh][njp]) << 4);
                    ldsm4(Bh4[njp], bBase[nh][njp] + bo);
                    if (NB == 2) ldsm4(Bl4[njp], bBase[nh][njp] + bo + BSZ);
                }
#pragma unroll
                for (int nj = 0; nj < 4; nj++) {
                    int njp = nj >> 1, hi = (nj & 1) * 2;
                    unsigned bfh[2] = { Bh4[njp][hi], Bh4[njp][hi + 1] };
#pragma unroll
                    for (int mi = 0; mi < 4; mi++) {
                        float* c = acc[mi][nh * 4 + nj];
                        MMA<ET>::run(c, Ah[mi], bfh);
                        if (NA == 2) MMA<ET>::run(c, Al[mi], bfh);
                        if (NB == 2) {
                            unsigned bfl[2] = { Bl4[njp][hi], Bl4[njp][hi + 1] };
                            MMA<ET>::run(c, Ah[mi], bfl);
                        }
                    }
                }
            }
        }
    };

    CPA(0, 0); CPB(0, 0); CP_COMMIT;
    CP_WAIT0;
    __syncthreads();

    for (int s = 0; s < nst; s++) {
        if (s + 1 < nst) { CPA((s + 1) * KT, (s + 1) & 1); CPB((s + 1) * KT, (s + 1) & 1); CP_COMMIT; }
        COMPUTE(s & 1);
        if (s + 1 < nst) CP_WAIT0;
        __syncthreads();
    }

#pragma unroll
    for (int mi = 0; mi < 4; mi++)
#pragma unroll
        for (int ni = 0; ni < 8; ni++) {
            int row0 = m0 + wm * 64 + mi * 16 + g;
            int col0 = n0 + wn * 64 + ni * 8 + 2 * tig;
            float* c = acc[mi][ni];
            if (col0 < Nv)     epiM<EP>(p, bz, row0,     col0,     c[0]);
            if (col0 + 1 < Nv) epiM<EP>(p, bz, row0,     col0 + 1, c[1]);
            if (col0 < Nv)     epiM<EP>(p, bz, row0 + 8, col0,     c[2]);
            if (col0 + 1 < Nv) epiM<EP>(p, bz, row0 + 8, col0 + 1, c[3]);
        }
}

// ---------------- launch ----------------
constexpr int SMM3 = 2 * (2 * 256 * 128 + 2 * 128 * 128);  // 196608
constexpr int SMM2 = 2 * (2 * 256 * 128 + 1 * 128 * 128);  // 163840
constexpr int SMM1 = 2 * (1 * 256 * 128 + 1 * 128 * 128);  // 98304
typedef __nv_bfloat16 BF;
typedef __half HF;

extern "C" void kernel_launch(void* const* d_in, const int* in_sizes, int n_in,
                              void* d_out, int out_size) {
    (void)in_sizes; (void)n_in; (void)out_size;
    const float* x    = (const float*)d_in[0];
    const float* ln_s = (const float*)d_in[1];
    const float* ln_b = (const float*)d_in[2];
    const float* v_w  = (const float*)d_in[3];
    const float* v_b  = (const float*)d_in[4];
    const float* mx_w = (const float*)d_in[5];
    const float* mx_b = (const float*)d_in[6];
    const float* h_w  = (const float*)d_in[7];
    const float* h_b  = (const float*)d_in[8];
    const float* gamma= (const float*)d_in[9];
    const float* beta = (const float*)d_in[10];
    const float* rel  = (const float*)d_in[11];
    const float* e_d  = (const float*)d_in[12];
    const float* e_a  = (const float*)d_in[13];
    const float* e_b  = (const float*)d_in[14];
    const float* e_g  = (const float*)d_in[15];
    const float* e_o  = (const float*)d_in[16];
    const float* f_s  = (const float*)d_in[17];
    const float* f_b  = (const float*)d_in[18];
    const float* w1   = (const float*)d_in[19];
    const float* b1   = (const float*)d_in[20];
    const float* w2   = (const float*)d_in[21];
    const float* b2   = (const float*)d_in[22];

    HF *p_xnh, *p_sch, *p_hrh, *p_olh, *p_inh, *p_mxh, *p_mxl;
    HF *p_vh, *p_wvh, *p_whh, *p_w1h, *p_w2h, *p_wmh;
    BF *p_qh, *p_ql, *p_kh, *p_kl;
    cudaGetSymbolAddress((void**)&p_xnh, g_xnh);
    cudaGetSymbolAddress((void**)&p_sch, g_sch);
    cudaGetSymbolAddress((void**)&p_hrh, g_hrh);
    cudaGetSymbolAddress((void**)&p_olh, g_olh);
    cudaGetSymbolAddress((void**)&p_inh, g_inh);
    cudaGetSymbolAddress((void**)&p_mxh, g_mxh);
    cudaGetSymbolAddress((void**)&p_mxl, g_mxl);
    cudaGetSymbolAddress((void**)&p_vh,  g_vh);
    cudaGetSymbolAddress((void**)&p_wvh, g_wvh);
    cudaGetSymbolAddress((void**)&p_whh, g_whh);
    cudaGetSymbolAddress((void**)&p_w1h, g_w1h);
    cudaGetSymbolAddress((void**)&p_w2h, g_w2h);
    cudaGetSymbolAddress((void**)&p_wmh, g_wmh);
    cudaGetSymbolAddress((void**)&p_qh,  g_qh);
    cudaGetSymbolAddress((void**)&p_ql,  g_ql);
    cudaGetSymbolAddress((void**)&p_kh,  g_kh);
    cudaGetSymbolAddress((void**)&p_kl,  g_kl);

    cudaFuncSetAttribute(k_mgemm<MP_V,    1, HF>, cudaFuncAttributeMaxDynamicSharedMemorySize, SMM1);
    cudaFuncSetAttribute(k_mgemm<MP_BASE, 2, HF>, cudaFuncAttributeMaxDynamicSharedMemorySize, SMM2);
    cudaFuncSetAttribute(k_mgemm<MP_SC,   3, BF>, cudaFuncAttributeMaxDynamicSharedMemorySize, SMM3);
    cudaFuncSetAttribute(k_mgemm<MP_HR,   1, HF>, cudaFuncAttributeMaxDynamicSharedMemorySize, SMM1);
    cudaFuncSetAttribute(k_mgemm<MP_H2,   1, HF>, cudaFuncAttributeMaxDynamicSharedMemorySize, SMM1);
    cudaFuncSetAttribute(k_mgemm<MP_RELU, 1, HF>, cudaFuncAttributeMaxDynamicSharedMemorySize, SMM1);
    cudaFuncSetAttribute(k_mgemm<MP_FIN,  1, HF>, cudaFuncAttributeMaxDynamicSharedMemorySize, SMM1);

    // weight prep
    k_wt<HF, false><<<dim3(Hh / 32, Dd / 32), 256>>>(v_w, p_wvh, nullptr, Dd, Hh);
    k_wt<HF, false><<<dim3(NMX / 32, Dd / 32), 256>>>(mx_w, p_wmh, nullptr, Dd, NMX);
    k_wt<HF, false><<<dim3(Dd / 32, Hh / 32), 256>>>(h_w, p_whh, nullptr, Hh, Dd);
    k_wt<HF, false><<<dim3(II / 32, Dd / 32), 256>>>(w1, p_w1h, nullptr, Dd, II);
    k_wt<HF, false><<<dim3(Dd / 32, II / 32), 256>>>(w2, p_w2h, nullptr, II, Dd);

    k_ln1<<<SB, 256>>>(x, ln_s, ln_b);
    k_ema<<<(Bb * Dd) / 16, 256>>>(e_d, e_a, e_b, e_g, e_o);

    TG p;
    // v = silu(xn @ v_w + v_b) -> v^T fp16  (1-term)
    p = {p_xnh, nullptr, p_wvh, nullptr, v_b, nullptr, nullptr, nullptr, Dd, Hh, 0, 0};
    k_mgemm<MP_V, 1, HF><<<dim3(Hh / 128, SB / 256, 1), 256, SMM1>>>(p);
    // base = mx @ mx_w + mx_b -> u,(q,k),r,hx  (2-term fp16)
    p = {p_mxh, p_mxl, p_wmh, nullptr, mx_b, gamma, beta, nullptr, Dd, NMX, 0, 0};
    k_mgemm<MP_BASE, 2, HF><<<dim3(NMX / 128, SB / 256, 1), 256, SMM2>>>(p);
    // scores = scaling * q @ k^T + relpos  (3-term bf16, batched)
    p = {p_qh, p_ql, p_kh, p_kl, nullptr, rel, nullptr, nullptr, Zz, Ss, (long long)Ss * Zz, (long long)Ss * Zz};
    k_mgemm<MP_SC, 3, BF><<<dim3(Ss / 128, Ss / 256, Bb), 256, SMM3>>>(p);
    k_softmax<<<Bb * Ss, 256>>>();
    // hr = (attn @ v) * r  (1-term fp16, batched, fused)
    p = {p_sch, nullptr, p_vh, nullptr, nullptr, nullptr, nullptr, nullptr, Ss, Hh, (long long)Ss * Ss, (long long)Hh * Ss};
    k_mgemm<MP_HR, 1, HF><<<dim3(Hh / 128, Ss / 256, Bb), 256, SMM1>>>(p);
    // h2 = silu(hx + hr @ h_w + h_b)  (1-term fp16)
    p = {p_hrh, nullptr, p_whh, nullptr, h_b, nullptr, nullptr, nullptr, Hh, Dd, 0, 0};
    k_mgemm<MP_H2, 1, HF><<<dim3(Dd / 128, SB / 256, 1), 256, SMM1>>>(p);
    k_gateln<<<SB, 256>>>(f_s, f_b);
    // FFN  (1-term fp16)
    p = {p_olh, nullptr, p_w1h, nullptr, b1, nullptr, nullptr, nullptr, Dd, II, 0, 0};
    k_mgemm<MP_RELU, 1, HF><<<dim3(II / 128, SB / 256, 1), 256, SMM1>>>(p);
    p = {p_inh, nullptr, p_w2h, nullptr, b2, nullptr, nullptr, (float*)d_out, II, Dd, 0, 0};
    k_mgemm<MP_FIN, 1, HF><<<dim3(Dd / 128, SB / 256, 1), 256, SMM1>>>(p);
}

// round 15
// speedup vs baseline: 1.7059x; 1.0824x over previous
#include <cuda_runtime.h>
#include <cuda_bf16.h>
#include <cuda_fp16.h>
#include <math.h>

#define DEVFN __device__ __forceinline__
#define DG __device__ __align__(128)

constexpr int Bb = 8, Ss = 2048, Dd = 1024, Zz = 128, Nn = 16, Hh = 2048, II = 4096, MPc = 2048;
constexpr int SB = Ss * Bb;
constexpr int NMX = Dd + Zz + Hh + Dd;  // 4224
constexpr float EPS = 1e-3f;
constexpr float SCALING = 0.08838834764831843f;

// ---------------- scratch ----------------
DG float g_u [(size_t)SB * Dd];
DG float g_hx[(size_t)SB * Dd];
DG float g_r [(size_t)SB * Hh];
DG float g_sc[(size_t)Bb * Ss * Ss];
DG float g_h2[(size_t)SB * Dd];
DG float g_ol[(size_t)SB * Dd];
// fp16 A operands
DG __half g_xnh[(size_t)SB * Dd];
DG __half g_mxh[(size_t)SB * Dd];
DG __half g_sch[(size_t)Bb * Ss * Ss];
DG __half g_hrh[(size_t)SB * Hh];
DG __half g_olh[(size_t)SB * Dd];
DG __half g_inh[(size_t)SB * II];
// fp16 B operands
DG __half g_vh [(size_t)Bb * Hh * Ss];
DG __half g_wvh[(size_t)Hh * Dd];
DG __half g_whh[(size_t)Dd * Hh];
DG __half g_w1h[(size_t)II * Dd];
DG __half g_w2h[(size_t)Dd * II];
DG __half g_wmh[(size_t)NMX * Dd];
// bf16 split operands (3-term scores GEMM)
DG __nv_bfloat16 g_qh[(size_t)Bb * Ss * Zz], g_ql[(size_t)Bb * Ss * Zz];
DG __nv_bfloat16 g_kh[(size_t)Bb * Ss * Zz], g_kl[(size_t)Bb * Ss * Zz];

// ---------------- helpers ----------------
DEVFN float sigm(float x) { return 1.f / (1.f + __expf(-x)); }
DEVFN float silu(float x) { return x / (1.f + __expf(-x)); }
DEVFN void splitB(__nv_bfloat16* oh, __nv_bfloat16* ol, size_t i, float v) {
    __nv_bfloat16 h = __float2bfloat16(v);
    oh[i] = h;
    ol[i] = __float2bfloat16(v - __bfloat162float(h));
}
DEVFN float warpSum(float v) {
#pragma unroll
    for (int o = 16; o; o >>= 1) v += __shfl_xor_sync(~0u, v, o);
    return v;
}
DEVFN float warpMax(float v) {
#pragma unroll
    for (int o = 16; o; o >>= 1) v = fmaxf(v, __shfl_xor_sync(~0u, v, o));
    return v;
}
DEVFN void blockSum2(float& a, float& b) {
    __shared__ float sa[8], sb_[8];
    float wa = warpSum(a), wb = warpSum(b);
    if ((threadIdx.x & 31) == 0) { sa[threadIdx.x >> 5] = wa; sb_[threadIdx.x >> 5] = wb; }
    __syncthreads();
    a = b = 0.f;
#pragma unroll
    for (int i = 0; i < 8; i++) { a += sa[i]; b += sb_[i]; }
    __syncthreads();
}
DEVFN float blockSum1(float v) {
    __shared__ float s[8];
    float w = warpSum(v);
    if ((threadIdx.x & 31) == 0) s[threadIdx.x >> 5] = w;
    __syncthreads();
    float r = 0.f;
#pragma unroll
    for (int i = 0; i < 8; i++) r += s[i];
    __syncthreads();
    return r;
}
DEVFN float blockMax1(float v) {
    __shared__ float s[8];
    float w = warpMax(v);
    if ((threadIdx.x & 31) == 0) s[threadIdx.x >> 5] = w;
    __syncthreads();
    float r = s[0];
#pragma unroll
    for (int i = 1; i < 8; i++) r = fmaxf(r, s[i]);
    __syncthreads();
    return r;
}

template<typename ET> struct MMA;
template<> struct MMA<__nv_bfloat16> {
    static DEVFN void run(float* c, const unsigned* a, const unsigned* b) {
        asm volatile(
            "mma.sync.aligned.m16n8k16.row.col.f32.bf16.bf16.f32 "
            "{%0,%1,%2,%3},{%4,%5,%6,%7},{%8,%9},{%0,%1,%2,%3};"
            : "+f"(c[0]), "+f"(c[1]), "+f"(c[2]), "+f"(c[3])
            : "r"(a[0]), "r"(a[1]), "r"(a[2]), "r"(a[3]), "r"(b[0]), "r"(b[1]));
    }
};
template<> struct MMA<__half> {
    static DEVFN void run(float* c, const unsigned* a, const unsigned* b) {
        asm volatile(
            "mma.sync.aligned.m16n8k16.row.col.f32.f16.f16.f32 "
            "{%0,%1,%2,%3},{%4,%5,%6,%7},{%8,%9},{%0,%1,%2,%3};"
            : "+f"(c[0]), "+f"(c[1]), "+f"(c[2]), "+f"(c[3])
            : "r"(a[0]), "r"(a[1]), "r"(a[2]), "r"(a[3]), "r"(b[0]), "r"(b[1]));
    }
};

DEVFN void ldsm4(unsigned* r, unsigned addr) {
    asm volatile("ldmatrix.sync.aligned.m8n8.x4.shared.b16 {%0,%1,%2,%3}, [%4];"
                 : "=r"(r[0]), "=r"(r[1]), "=r"(r[2]), "=r"(r[3]) : "r"(addr));
}
DEVFN void cpa16(unsigned dst, const void* src) {
    asm volatile("cp.async.cg.shared.global [%0], [%1], 16;" :: "r"(dst), "l"(src) : "memory");
}
#define CP_COMMIT asm volatile("cp.async.commit_group;" ::: "memory")
#define CP_WAIT0  asm volatile("cp.async.wait_group 0;" ::: "memory")
DEVFN unsigned smem_u32(const void* p) {
    unsigned a;
    asm("{ .reg .u64 t; cvta.to.shared.u64 t, %1; cvt.u32.u64 %0, t; }" : "=r"(a) : "l"(p));
    return a;
}

// ---------------- elementwise ----------------
__global__ __launch_bounds__(256) void k_ln1(const float* __restrict__ x,
                                             const float* __restrict__ sc,
                                             const float* __restrict__ bi) {
    int m = blockIdx.x, b = m / Ss, s = m % Ss, t = threadIdx.x;
    const float* xr = x + (size_t)m * Dd;
    float v[4], su = 0.f, sq = 0.f;
#pragma unroll
    for (int i = 0; i < 4; i++) { float f = xr[t + 256 * i]; v[i] = f; su += f; sq += f * f; }
    blockSum2(su, sq);
    float mu = su * (1.f / Dd), inv = rsqrtf(sq * (1.f / Dd) - mu * mu + EPS);
    size_t base = (size_t)(s * Bb + b) * Dd;
#pragma unroll
    for (int i = 0; i < 4; i++) {
        int d = t + 256 * i;
        float val = (v[i] - mu) * inv * sc[d] + bi[d];
        g_xnh[base + d] = __float2half_rn(val);
    }
}

__global__ __launch_bounds__(256) void k_ema(const float* __restrict__ de, const float* __restrict__ al,
                                             const float* __restrict__ be, const float* __restrict__ ga,
                                             const float* __restrict__ om) {
    int t = threadIdx.x, lane = t & 15;
    int P = blockIdx.x * 16 + (t >> 4), b = P / Dd, d = P % Dd;
    int pi = d * Nn + lane;
    float p = sigm(de[pi]);
    float q = 1.f - p * sigm(al[pi]);
    float coef = p * be[pi] * ga[pi] * 0.25f;
    float w = om[d];
    const __half* xp = g_xnh + (size_t)b * Dd + d;
    size_t obase = (size_t)b * Dd + d;
    float s = 0.f;
    for (int l = 0; l < Ss; l++) {
        float xv = __half2float(xp[(size_t)l * (Bb * Dd)]);
        s = fmaf(q, s, xv);
        float r = coef * s;
        r += __shfl_xor_sync(~0u, r, 1);
        r += __shfl_xor_sync(~0u, r, 2);
        r += __shfl_xor_sync(~0u, r, 4);
        r += __shfl_xor_sync(~0u, r, 8);
        if (lane == 0)
            g_mxh[obase + (size_t)l * (Bb * Dd)] = __float2half_rn(silu(r + xv * w));
    }
}

__global__ __launch_bounds__(256) void k_softmax() {
    size_t rbase = (size_t)blockIdx.x * Ss;
    const float* rp = g_sc + rbase;
    int t = threadIdx.x;
    float v[8], mx = -1e30f;
#pragma unroll
    for (int i = 0; i < 8; i++) { v[i] = rp[t + 256 * i]; mx = fmaxf(mx, v[i]); }
    mx = blockMax1(mx);
    float su = 0.f;
#pragma unroll
    for (int i = 0; i < 8; i++) { v[i] = __expf(v[i] - mx); su += v[i]; }
    su = blockSum1(su);
    float inv = 1.f / su;
#pragma unroll
    for (int i = 0; i < 8; i++)
        g_sch[rbase + t + 256 * i] = __float2half_rn(v[i] * inv);
}

__global__ __launch_bounds__(256) void k_gateln(const float* __restrict__ sc,
                                                const float* __restrict__ bi) {
    int m = blockIdx.x, s = m >> 3, b = m & 7, t = threadIdx.x;
    size_t base = (size_t)m * Dd;
    float g[4], su = 0.f, sq = 0.f;
#pragma unroll
    for (int i = 0; i < 4; i++) {
        int d = t + 256 * i;
        float xn = __half2float(g_xnh[base + d]);
        float val = xn + g_u[base + d] * (g_h2[base + d] - xn);
        g[i] = val; su += val; sq += val * val;
    }
    blockSum2(su, sq);
    float mu = su * (1.f / Dd), inv = rsqrtf(sq * (1.f / Dd) - mu * mu + EPS);
    size_t ob = ((size_t)b * Ss + s) * Dd;
#pragma unroll
    for (int i = 0; i < 4; i++) {
        int d = t + 256 * i;
        float val = (g[i] - mu) * inv * sc[d] + bi[d];
        g_ol[ob + d] = val;
        g_olh[ob + d] = __float2half_rn(val);
    }
}

template<typename T, bool LO>
__global__ __launch_bounds__(256) void k_wt(const float* __restrict__ W,
                                            T* __restrict__ oh,
                                            T* __restrict__ ol, int K, int N) {
    __shared__ float tl[32][33];
    int n0 = blockIdx.x * 32, k0 = blockIdx.y * 32;
    int tx = threadIdx.x & 31, ty = threadIdx.x >> 5;
#pragma unroll
    for (int i = 0; i < 4; i++) tl[ty + i * 8][tx] = W[(size_t)(k0 + ty + i * 8) * N + n0 + tx];
    __syncthreads();
#pragma unroll
    for (int i = 0; i < 4; i++) {
        int ny = ty + i * 8;
        float v = tl[tx][ny];
        size_t o = (size_t)(n0 + ny) * K + k0 + tx;
        T h = (T)v;
        oh[o] = h;
        if (LO) ol[o] = (T)(v - (float)h);
    }
}

// ================= mma.sync GEMM (TM=256,TN=128, KT=64) =================
struct TG {
    const void* Ah; const void* Al;
    const void* Bh; const void* Bl;
    const float* bias; const float* aux; const float* aux2;
    float* out;
    int K, Nv;
    long long sA, sB;
};

enum { MP_V = 0, MP_BASE, MP_SC, MP_HR, MP_H2, MP_RELU, MP_FIN };

template<int EP>
DEVFN void epiM(const TG& p, int bz, int m, int n, float acc) {
    if (EP == MP_V) {
        float v = silu(acc + p.bias[n]);
        int s = m >> 3, b = m & 7;
        g_vh[((size_t)(b * Hh + n)) * Ss + s] = __float2half_rn(v);
    } else if (EP == MP_BASE) {
        float a = acc + p.bias[n];
        if (n < Dd) {
            g_u[(size_t)m * Dd + n] = sigm(a);
        } else if (n < Dd + Zz) {
            float z = silu(a); int zi = n - Dd;
            int s = m >> 3, b = m & 7;
            size_t o = ((size_t)(b * Ss + s)) * Zz + zi;
            splitB(g_qh, g_ql, o, z * p.aux[zi] + p.aux2[zi]);
            splitB(g_kh, g_kl, o, z * p.aux[Zz + zi] + p.aux2[Zz + zi]);
        } else if (n < Dd + Zz + Hh) {
            g_r[(size_t)m * Hh + (n - Dd - Zz)] = silu(a);
        } else {
            g_hx[(size_t)m * Dd + (n - Dd - Zz - Hh)] = a;
        }
    } else if (EP == MP_SC) {
        g_sc[((size_t)bz * Ss + m) * Ss + n] = acc * SCALING + p.aux[MPc - 1 + n - m];
    } else if (EP == MP_HR) {
        size_t o = ((size_t)(m * Bb + bz)) * Hh + n;
        g_hrh[o] = __float2half_rn(acc * g_r[o]);
    } else if (EP == MP_H2) {
        g_h2[(size_t)m * Dd + n] = silu(acc + p.bias[n] + g_hx[(size_t)m * Dd + n]);
    } else if (EP == MP_RELU) {
        g_inh[(size_t)m * II + n] = __float2half_rn(fmaxf(acc + p.bias[n], 0.f));
    } else {
        p.out[(size_t)m * Dd + n] = acc + p.bias[n] + g_ol[(size_t)m * Dd + n];
    }
}

// CTA 256x128, warp 64x64 (4m x 2n), K-chunk 64, double-buffered, cp.async-fed.
// TERMS=3: Ah*Bh+Al*Bh+Ah*Bl (bf16). TERMS=2: Ah*Bh+Al*Bh. TERMS=1: Ah*Bh.
template<int EP, int TERMS, typename ET>
__global__ void __launch_bounds__(256, 1) k_mgemm(TG p) {
    constexpr int TM = 256, TN = 128;
    constexpr int ASZ = TM * 128;
    constexpr int BSZ = TN * 128;
    constexpr int NA = (TERMS >= 2) ? 2 : 1;
    constexpr int NB = (TERMS == 3) ? 2 : 1;
    constexpr int STGB = NA * ASZ + NB * BSZ;
    constexpr int KT = 64;

    extern __shared__ char sm[];
    const unsigned sb = smem_u32(sm);

    const int t = threadIdx.x, lane = t & 31, wid = t >> 5;
    const int wm = wid & 3, wn = wid >> 2;
    const int g = lane >> 2, tig = lane & 3;
    const int bz = blockIdx.z;
    const int m0 = blockIdx.y * TM, n0 = blockIdx.x * TN;
    const ET* Ahp = (const ET*)p.Ah + (size_t)bz * (size_t)p.sA;
    const ET* Alp = (NA == 2) ? ((const ET*)p.Al + (size_t)bz * (size_t)p.sA) : nullptr;
    const ET* Bhp = (const ET*)p.Bh + (size_t)bz * (size_t)p.sB;
    const ET* Blp = (NB == 2) ? ((const ET*)p.Bl + (size_t)bz * (size_t)p.sB) : nullptr;
    const int K = p.K;
    const int nst = K / KT;
    const int Nv = p.Nv;

    const int matq = lane >> 3, r8 = lane & 7;
    const int amq = matq >> 1, bmq = matq & 1;
    unsigned aBase[4]; int aswz[4];
#pragma unroll
    for (int mi = 0; mi < 4; mi++) {
        int arow = wm * 64 + mi * 16 + (matq & 1) * 8 + r8;
        aBase[mi] = sb + arow * 128;
        aswz[mi] = arow & 7;
    }
    unsigned bBase[2][2]; int bswz[2][2];
#pragma unroll
    for (int nh = 0; nh < 2; nh++)
#pragma unroll
        for (int njp = 0; njp < 2; njp++) {
            int brow = wn * 64 + nh * 32 + njp * 16 + (matq >> 1) * 8 + r8;
            bBase[nh][njp] = sb + NA * ASZ + brow * 128;
            bswz[nh][njp] = brow & 7;
        }

    float acc[4][8][4];
#pragma unroll
    for (int i = 0; i < 4; i++)
#pragma unroll
        for (int j = 0; j < 8; j++)
#pragma unroll
            for (int r = 0; r < 4; r++) acc[i][j][r] = 0.f;

    auto CPA = [&](int k0, int buf) {
        unsigned ah = sb + buf * STGB, al = ah + ASZ;
#pragma unroll
        for (int j = 0; j < 8; j++) {
            int idx = t + 256 * j;
            int row = idx >> 3, q = idx & 7;
            unsigned off = row * 128 + ((q ^ (row & 7)) << 4);
            size_t go = (size_t)(m0 + row) * K + k0 + q * 8;
            cpa16(ah + off, Ahp + go);
            if (NA == 2) cpa16(al + off, Alp + go);
        }
    };
    auto CPB = [&](int k0, int buf) {
        unsigned bh = sb + buf * STGB + NA * ASZ, bl = bh + BSZ;
#pragma unroll
        for (int j = 0; j < 4; j++) {
            int idx = t + 256 * j;
            int row = idx >> 3, q = idx & 7;
            int rn = n0 + row; if (rn >= Nv) rn = Nv - 1;
            unsigned off = row * 128 + ((q ^ (row & 7)) << 4);
            size_t go = (size_t)rn * K + k0 + q * 8;
            cpa16(bh + off, Bhp + go);
            if (NB == 2) cpa16(bl + off, Blp + go);
        }
    };

    auto COMPUTE = [&](int buf) {
        const unsigned off = buf * STGB;
#pragma unroll
        for (int kk = 0; kk < 4; kk++) {
            unsigned Ah[4][4], Al[4][4];
#pragma unroll
            for (int mi = 0; mi < 4; mi++) {
                unsigned ao = off + (((kk * 2 + amq) ^ aswz[mi]) << 4);
                ldsm4(Ah[mi], aBase[mi] + ao);
                if (NA == 2) ldsm4(Al[mi], aBase[mi] + ao + ASZ);
            }
#pragma unroll
            for (int nh = 0; nh < 2; nh++) {
                unsigned Bh4[2][4], Bl4[2][4];
#pragma unroll
                for (int njp = 0; njp < 2; njp++) {
                    unsigned bo = off + (((kk * 2 + bmq) ^ bswz[nh][njp]) << 4);
                    ldsm4(Bh4[njp], bBase[nh][njp] + bo);
                    if (NB == 2) ldsm4(Bl4[njp], bBase[nh][njp] + bo + BSZ);
                }
#pragma unroll
                for (int nj = 0; nj < 4; nj++) {
                    int njp = nj >> 1, hi = (nj & 1) * 2;
                    unsigned bfh[2] = { Bh4[njp][hi], Bh4[njp][hi + 1] };
#pragma unroll
                    for (int mi = 0; mi < 4; mi++) {
                        float* c = acc[mi][nh * 4 + nj];
                        MMA<ET>::run(c, Ah[mi], bfh);
                        if (NA == 2) MMA<ET>::run(c, Al[mi], bfh);
                        if (NB == 2) {
                            unsigned bfl[2] = { Bl4[njp][hi], Bl4[njp][hi + 1] };
                            MMA<ET>::run(c, Ah[mi], bfl);
                        }
                    }
                }
            }
        }
    };

    CPA(0, 0); CPB(0, 0); CP_COMMIT;
    CP_WAIT0;
    __syncthreads();

    for (int s = 0; s < nst; s++) {
        if (s + 1 < nst) { CPA((s + 1) * KT, (s + 1) & 1); CPB((s + 1) * KT, (s + 1) & 1); CP_COMMIT; }
        COMPUTE(s & 1);
        if (s + 1 < nst) CP_WAIT0;
        __syncthreads();
    }

#pragma unroll
    for (int mi = 0; mi < 4; mi++)
#pragma unroll
        for (int ni = 0; ni < 8; ni++) {
            int row0 = m0 + wm * 64 + mi * 16 + g;
            int col0 = n0 + wn * 64 + ni * 8 + 2 * tig;
            float* c = acc[mi][ni];
            if (col0 < Nv)     epiM<EP>(p, bz, row0,     col0,     c[0]);
            if (col0 + 1 < Nv) epiM<EP>(p, bz, row0,     col0 + 1, c[1]);
            if (col0 < Nv)     epiM<EP>(p, bz, row0 + 8, col0,     c[2]);
            if (col0 + 1 < Nv) epiM<EP>(p, bz, row0 + 8, col0 + 1, c[3]);
        }
}

// ---------------- launch ----------------
constexpr int SMM3 = 2 * (2 * 256 * 128 + 2 * 128 * 128);  // 196608
constexpr int SMM1 = 2 * (1 * 256 * 128 + 1 * 128 * 128);  // 98304
typedef __nv_bfloat16 BF;
typedef __half HF;

extern "C" void kernel_launch(void* const* d_in, const int* in_sizes, int n_in,
                              void* d_out, int out_size) {
    (void)in_sizes; (void)n_in; (void)out_size;
    const float* x    = (const float*)d_in[0];
    const float* ln_s = (const float*)d_in[1];
    const float* ln_b = (const float*)d_in[2];
    const float* v_w  = (const float*)d_in[3];
    const float* v_b  = (const float*)d_in[4];
    const float* mx_w = (const float*)d_in[5];
    const float* mx_b = (const float*)d_in[6];
    const float* h_w  = (const float*)d_in[7];
    const float* h_b  = (const float*)d_in[8];
    const float* gamma= (const float*)d_in[9];
    const float* beta = (const float*)d_in[10];
    const float* rel  = (const float*)d_in[11];
    const float* e_d  = (const float*)d_in[12];
    const float* e_a  = (const float*)d_in[13];
    const float* e_b  = (const float*)d_in[14];
    const float* e_g  = (const float*)d_in[15];
    const float* e_o  = (const float*)d_in[16];
    const float* f_s  = (const float*)d_in[17];
    const float* f_b  = (const float*)d_in[18];
    const float* w1   = (const float*)d_in[19];
    const float* b1   = (const float*)d_in[20];
    const float* w2   = (const float*)d_in[21];
    const float* b2   = (const float*)d_in[22];

    HF *p_xnh, *p_mxh, *p_sch, *p_hrh, *p_olh, *p_inh;
    HF *p_vh, *p_wvh, *p_whh, *p_w1h, *p_w2h, *p_wmh;
    BF *p_qh, *p_ql, *p_kh, *p_kl;
    cudaGetSymbolAddress((void**)&p_xnh, g_xnh);
    cudaGetSymbolAddress((void**)&p_mxh, g_mxh);
    cudaGetSymbolAddress((void**)&p_sch, g_sch);
    cudaGetSymbolAddress((void**)&p_hrh, g_hrh);
    cudaGetSymbolAddress((void**)&p_olh, g_olh);
    cudaGetSymbolAddress((void**)&p_inh, g_inh);
    cudaGetSymbolAddress((void**)&p_vh,  g_vh);
    cudaGetSymbolAddress((void**)&p_wvh, g_wvh);
    cudaGetSymbolAddress((void**)&p_whh, g_whh);
    cudaGetSymbolAddress((void**)&p_w1h, g_w1h);
    cudaGetSymbolAddress((void**)&p_w2h, g_w2h);
    cudaGetSymbolAddress((void**)&p_wmh, g_wmh);
    cudaGetSymbolAddress((void**)&p_qh,  g_qh);
    cudaGetSymbolAddress((void**)&p_ql,  g_ql);
    cudaGetSymbolAddress((void**)&p_kh,  g_kh);
    cudaGetSymbolAddress((void**)&p_kl,  g_kl);

    cudaFuncSetAttribute(k_mgemm<MP_V,    1, HF>, cudaFuncAttributeMaxDynamicSharedMemorySize, SMM1);
    cudaFuncSetAttribute(k_mgemm<MP_BASE, 1, HF>, cudaFuncAttributeMaxDynamicSharedMemorySize, SMM1);
    cudaFuncSetAttribute(k_mgemm<MP_SC,   3, BF>, cudaFuncAttributeMaxDynamicSharedMemorySize, SMM3);
    cudaFuncSetAttribute(k_mgemm<MP_HR,   1, HF>, cudaFuncAttributeMaxDynamicSharedMemorySize, SMM1);
    cudaFuncSetAttribute(k_mgemm<MP_H2,   1, HF>, cudaFuncAttributeMaxDynamicSharedMemorySize, SMM1);
    cudaFuncSetAttribute(k_mgemm<MP_RELU, 1, HF>, cudaFuncAttributeMaxDynamicSharedMemorySize, SMM1);
    cudaFuncSetAttribute(k_mgemm<MP_FIN,  1, HF>, cudaFuncAttributeMaxDynamicSharedMemorySize, SMM1);

    // weight prep
    k_wt<HF, false><<<dim3(Hh / 32, Dd / 32), 256>>>(v_w, p_wvh, nullptr, Dd, Hh);
    k_wt<HF, false><<<dim3(NMX / 32, Dd / 32), 256>>>(mx_w, p_wmh, nullptr, Dd, NMX);
    k_wt<HF, false><<<dim3(Dd / 32, Hh / 32), 256>>>(h_w, p_whh, nullptr, Hh, Dd);
    k_wt<HF, false><<<dim3(II / 32, Dd / 32), 256>>>(w1, p_w1h, nullptr, Dd, II);
    k_wt<HF, false><<<dim3(Dd / 32, II / 32), 256>>>(w2, p_w2h, nullptr, II, Dd);

    k_ln1<<<SB, 256>>>(x, ln_s, ln_b);
    k_ema<<<(Bb * Dd) / 16, 256>>>(e_d, e_a, e_b, e_g, e_o);

    TG p;
    // v = silu(xn @ v_w + v_b) -> v^T fp16  (1-term)
    p = {p_xnh, nullptr, p_wvh, nullptr, v_b, nullptr, nullptr, nullptr, Dd, Hh, 0, 0};
    k_mgemm<MP_V, 1, HF><<<dim3(Hh / 128, SB / 256, 1), 256, SMM1>>>(p);
    // base = mx @ mx_w + mx_b -> u,(q,k),r,hx  (1-term fp16)
    p = {p_mxh, nullptr, p_wmh, nullptr, mx_b, gamma, beta, nullptr, Dd, NMX, 0, 0};
    k_mgemm<MP_BASE, 1, HF><<<dim3(NMX / 128, SB / 256, 1), 256, SMM1>>>(p);
    // scores = scaling * q @ k^T + relpos  (3-term bf16, batched)
    p = {p_qh, p_ql, p_kh, p_kl, nullptr, rel, nullptr, nullptr, Zz, Ss, (long long)Ss * Zz, (long long)Ss * Zz};
    k_mgemm<MP_SC, 3, BF><<<dim3(Ss / 128, Ss / 256, Bb), 256, SMM3>>>(p);
    k_softmax<<<Bb * Ss, 256>>>();
    // hr = (attn @ v) * r  (1-term fp16, batched, fused)
    p = {p_sch, nullptr, p_vh, nullptr, nullptr, nullptr, nullptr, nullptr, Ss, Hh, (long long)Ss * Ss, (long long)Hh * Ss};
    k_mgemm<MP_HR, 1, HF><<<dim3(Hh / 128, Ss / 256, Bb), 256, SMM1>>>(p);
    // h2 = silu(hx + hr @ h_w + h_b)  (1-term fp16)
    p = {p_hrh, nullptr, p_whh, nullptr, h_b, nullptr, nullptr, nullptr, Hh, Dd, 0, 0};
    k_mgemm<MP_H2, 1, HF><<<dim3(Dd / 128, SB / 256, 1), 256, SMM1>>>(p);
    k_gateln<<<SB, 256>>>(f_s, f_b);
    // FFN  (1-term fp16)
    p = {p_olh, nullptr, p_w1h, nullptr, b1, nullptr, nullptr, nullptr, Dd, II, 0, 0};
    k_mgemm<MP_RELU, 1, HF><<<dim3(II / 128, SB / 256, 1), 256, SMM1>>>(p);
    p = {p_inh, nullptr, p_w2h, nullptr, b2, nullptr, nullptr, (float*)d_out, II, Dd, 0, 0};
    k_mgemm<MP_FIN, 1, HF><<<dim3(Dd / 128, SB / 256, 1), 256, SMM1>>>(p);
}

// round 16
// speedup vs baseline: 1.7244x; 1.0108x over previous
#include <cuda_runtime.h>
#include <cuda_bf16.h>
#include <cuda_fp16.h>
#include <math.h>

#define DEVFN __device__ __forceinline__
#define DG __device__ __align__(128)

constexpr int Bb = 8, Ss = 2048, Dd = 1024, Zz = 128, Nn = 16, Hh = 2048, II = 4096, MPc = 2048;
constexpr int SB = Ss * Bb;
constexpr int NMX = Dd + Zz + Hh + Dd;  // 4224
constexpr float EPS = 1e-3f;
constexpr float SCALING = 0.08838834764831843f;

// ---------------- scratch ----------------
DG float g_u [(size_t)SB * Dd];
DG float g_hx[(size_t)SB * Dd];
DG float g_r [(size_t)SB * Hh];
DG float g_sc[(size_t)Bb * Ss * Ss];
DG float g_h2[(size_t)SB * Dd];
DG float g_ol[(size_t)SB * Dd];
// fp16 A operands
DG __half g_xnh[(size_t)SB * Dd];
DG __half g_mxh[(size_t)SB * Dd];
DG __half g_sch[(size_t)Bb * Ss * Ss];
DG __half g_hrh[(size_t)SB * Hh];
DG __half g_olh[(size_t)SB * Dd];
DG __half g_inh[(size_t)SB * II];
// fp16 B operands
DG __half g_vh [(size_t)Bb * Hh * Ss];
DG __half g_wvh[(size_t)Hh * Dd];
DG __half g_whh[(size_t)Dd * Hh];
DG __half g_w1h[(size_t)II * Dd];
DG __half g_w2h[(size_t)Dd * II];
DG __half g_wmh[(size_t)NMX * Dd];
// bf16 split operands (3-term scores GEMM)
DG __nv_bfloat16 g_qh[(size_t)Bb * Ss * Zz], g_ql[(size_t)Bb * Ss * Zz];
DG __nv_bfloat16 g_kh[(size_t)Bb * Ss * Zz], g_kl[(size_t)Bb * Ss * Zz];

// ---------------- helpers ----------------
DEVFN float sigm(float x) { return 1.f / (1.f + __expf(-x)); }
DEVFN float silu(float x) { return x / (1.f + __expf(-x)); }
DEVFN void splitB(__nv_bfloat16* oh, __nv_bfloat16* ol, size_t i, float v) {
    __nv_bfloat16 h = __float2bfloat16(v);
    oh[i] = h;
    ol[i] = __float2bfloat16(v - __bfloat162float(h));
}
DEVFN float warpSum(float v) {
#pragma unroll
    for (int o = 16; o; o >>= 1) v += __shfl_xor_sync(~0u, v, o);
    return v;
}
DEVFN float warpMax(float v) {
#pragma unroll
    for (int o = 16; o; o >>= 1) v = fmaxf(v, __shfl_xor_sync(~0u, v, o));
    return v;
}
DEVFN void blockSum2(float& a, float& b) {
    __shared__ float sa[8], sb_[8];
    float wa = warpSum(a), wb = warpSum(b);
    if ((threadIdx.x & 31) == 0) { sa[threadIdx.x >> 5] = wa; sb_[threadIdx.x >> 5] = wb; }
    __syncthreads();
    a = b = 0.f;
#pragma unroll
    for (int i = 0; i < 8; i++) { a += sa[i]; b += sb_[i]; }
    __syncthreads();
}
DEVFN float blockSum1(float v) {
    __shared__ float s[8];
    float w = warpSum(v);
    if ((threadIdx.x & 31) == 0) s[threadIdx.x >> 5] = w;
    __syncthreads();
    float r = 0.f;
#pragma unroll
    for (int i = 0; i < 8; i++) r += s[i];
    __syncthreads();
    return r;
}
DEVFN float blockMax1(float v) {
    __shared__ float s[8];
    float w = warpMax(v);
    if ((threadIdx.x & 31) == 0) s[threadIdx.x >> 5] = w;
    __syncthreads();
    float r = s[0];
#pragma unroll
    for (int i = 1; i < 8; i++) r = fmaxf(r, s[i]);
    __syncthreads();
    return r;
}

template<typename ET> struct MMA;
template<> struct MMA<__nv_bfloat16> {
    static DEVFN void run(float* c, const unsigned* a, const unsigned* b) {
        asm volatile(
            "mma.sync.aligned.m16n8k16.row.col.f32.bf16.bf16.f32 "
            "{%0,%1,%2,%3},{%4,%5,%6,%7},{%8,%9},{%0,%1,%2,%3};"
            : "+f"(c[0]), "+f"(c[1]), "+f"(c[2]), "+f"(c[3])
            : "r"(a[0]), "r"(a[1]), "r"(a[2]), "r"(a[3]), "r"(b[0]), "r"(b[1]));
    }
};
template<> struct MMA<__half> {
    static DEVFN void run(float* c, const unsigned* a, const unsigned* b) {
        asm volatile(
            "mma.sync.aligned.m16n8k16.row.col.f32.f16.f16.f32 "
            "{%0,%1,%2,%3},{%4,%5,%6,%7},{%8,%9},{%0,%1,%2,%3};"
            : "+f"(c[0]), "+f"(c[1]), "+f"(c[2]), "+f"(c[3])
            : "r"(a[0]), "r"(a[1]), "r"(a[2]), "r"(a[3]), "r"(b[0]), "r"(b[1]));
    }
};

DEVFN void ldsm4(unsigned* r, unsigned addr) {
    asm volatile("ldmatrix.sync.aligned.m8n8.x4.shared.b16 {%0,%1,%2,%3}, [%4];"
                 : "=r"(r[0]), "=r"(r[1]), "=r"(r[2]), "=r"(r[3]) : "r"(addr));
}
DEVFN void cpa16(unsigned dst, const void* src) {
    asm volatile("cp.async.cg.shared.global [%0], [%1], 16;" :: "r"(dst), "l"(src) : "memory");
}
#define CP_COMMIT asm volatile("cp.async.commit_group;" ::: "memory")
#define CP_WAIT0  asm volatile("cp.async.wait_group 0;" ::: "memory")
#define CP_WAIT1  asm volatile("cp.async.wait_group 1;" ::: "memory")
DEVFN unsigned smem_u32(const void* p) {
    unsigned a;
    asm("{ .reg .u64 t; cvta.to.shared.u64 t, %1; cvt.u32.u64 %0, t; }" : "=r"(a) : "l"(p));
    return a;
}

// ---------------- elementwise ----------------
__global__ __launch_bounds__(256) void k_ln1(const float* __restrict__ x,
                                             const float* __restrict__ sc,
                                             const float* __restrict__ bi) {
    int m = blockIdx.x, b = m / Ss, s = m % Ss, t = threadIdx.x;
    const float* xr = x + (size_t)m * Dd;
    float v[4], su = 0.f, sq = 0.f;
#pragma unroll
    for (int i = 0; i < 4; i++) { float f = xr[t + 256 * i]; v[i] = f; su += f; sq += f * f; }
    blockSum2(su, sq);
    float mu = su * (1.f / Dd), inv = rsqrtf(sq * (1.f / Dd) - mu * mu + EPS);
    size_t base = (size_t)(s * Bb + b) * Dd;
#pragma unroll
    for (int i = 0; i < 4; i++) {
        int d = t + 256 * i;
        float val = (v[i] - mu) * inv * sc[d] + bi[d];
        g_xnh[base + d] = __float2half_rn(val);
    }
}

__global__ __launch_bounds__(256) void k_ema(const float* __restrict__ de, const float* __restrict__ al,
                                             const float* __restrict__ be, const float* __restrict__ ga,
                                             const float* __restrict__ om) {
    int t = threadIdx.x, lane = t & 15;
    int P = blockIdx.x * 16 + (t >> 4), b = P / Dd, d = P % Dd;
    int pi = d * Nn + lane;
    float p = sigm(de[pi]);
    float q = 1.f - p * sigm(al[pi]);
    float coef = p * be[pi] * ga[pi] * 0.25f;
    float w = om[d];
    const __half* xp = g_xnh + (size_t)b * Dd + d;
    size_t obase = (size_t)b * Dd + d;
    float s = 0.f;
    for (int l = 0; l < Ss; l++) {
        float xv = __half2float(xp[(size_t)l * (Bb * Dd)]);
        s = fmaf(q, s, xv);
        float r = coef * s;
        r += __shfl_xor_sync(~0u, r, 1);
        r += __shfl_xor_sync(~0u, r, 2);
        r += __shfl_xor_sync(~0u, r, 4);
        r += __shfl_xor_sync(~0u, r, 8);
        if (lane == 0)
            g_mxh[obase + (size_t)l * (Bb * Dd)] = __float2half_rn(silu(r + xv * w));
    }
}

__global__ __launch_bounds__(256) void k_softmax() {
    size_t rbase = (size_t)blockIdx.x * Ss;
    const float* rp = g_sc + rbase;
    int t = threadIdx.x;
    float v[8], mx = -1e30f;
#pragma unroll
    for (int i = 0; i < 8; i++) { v[i] = rp[t + 256 * i]; mx = fmaxf(mx, v[i]); }
    mx = blockMax1(mx);
    float su = 0.f;
#pragma unroll
    for (int i = 0; i < 8; i++) { v[i] = __expf(v[i] - mx); su += v[i]; }
    su = blockSum1(su);
    float inv = 1.f / su;
#pragma unroll
    for (int i = 0; i < 8; i++)
        g_sch[rbase + t + 256 * i] = __float2half_rn(v[i] * inv);
}

__global__ __launch_bounds__(256) void k_gateln(const float* __restrict__ sc,
                                                const float* __restrict__ bi) {
    int m = blockIdx.x, s = m >> 3, b = m & 7, t = threadIdx.x;
    size_t base = (size_t)m * Dd;
    float g[4], su = 0.f, sq = 0.f;
#pragma unroll
    for (int i = 0; i < 4; i++) {
        int d = t + 256 * i;
        float xn = __half2float(g_xnh[base + d]);
        float val = xn + g_u[base + d] * (g_h2[base + d] - xn);
        g[i] = val; su += val; sq += val * val;
    }
    blockSum2(su, sq);
    float mu = su * (1.f / Dd), inv = rsqrtf(sq * (1.f / Dd) - mu * mu + EPS);
    size_t ob = ((size_t)b * Ss + s) * Dd;
#pragma unroll
    for (int i = 0; i < 4; i++) {
        int d = t + 256 * i;
        float val = (g[i] - mu) * inv * sc[d] + bi[d];
        g_ol[ob + d] = val;
        g_olh[ob + d] = __float2half_rn(val);
    }
}

template<typename T, bool LO>
__global__ __launch_bounds__(256) void k_wt(const float* __restrict__ W,
                                            T* __restrict__ oh,
                                            T* __restrict__ ol, int K, int N) {
    __shared__ float tl[32][33];
    int n0 = blockIdx.x * 32, k0 = blockIdx.y * 32;
    int tx = threadIdx.x & 31, ty = threadIdx.x >> 5;
#pragma unroll
    for (int i = 0; i < 4; i++) tl[ty + i * 8][tx] = W[(size_t)(k0 + ty + i * 8) * N + n0 + tx];
    __syncthreads();
#pragma unroll
    for (int i = 0; i < 4; i++) {
        int ny = ty + i * 8;
        float v = tl[tx][ny];
        size_t o = (size_t)(n0 + ny) * K + k0 + tx;
        T h = (T)v;
        oh[o] = h;
        if (LO) ol[o] = (T)(v - (float)h);
    }
}

// ================= mma.sync GEMM (TM=256,TN=128, KT=64) =================
struct TG {
    const void* Ah; const void* Al;
    const void* Bh; const void* Bl;
    const float* bias; const float* aux; const float* aux2;
    float* out;
    int K, Nv;
    long long sA, sB;
};

enum { MP_V = 0, MP_BASE, MP_SC, MP_HR, MP_H2, MP_RELU, MP_FIN };

template<int EP>
DEVFN void epiM(const TG& p, int bz, int m, int n, float acc) {
    if (EP == MP_V) {
        float v = silu(acc + p.bias[n]);
        int s = m >> 3, b = m & 7;
        g_vh[((size_t)(b * Hh + n)) * Ss + s] = __float2half_rn(v);
    } else if (EP == MP_BASE) {
        float a = acc + p.bias[n];
        if (n < Dd) {
            g_u[(size_t)m * Dd + n] = sigm(a);
        } else if (n < Dd + Zz) {
            float z = silu(a); int zi = n - Dd;
            int s = m >> 3, b = m & 7;
            size_t o = ((size_t)(b * Ss + s)) * Zz + zi;
            splitB(g_qh, g_ql, o, z * p.aux[zi] + p.aux2[zi]);
            splitB(g_kh, g_kl, o, z * p.aux[Zz + zi] + p.aux2[Zz + zi]);
        } else if (n < Dd + Zz + Hh) {
            g_r[(size_t)m * Hh + (n - Dd - Zz)] = silu(a);
        } else {
            g_hx[(size_t)m * Dd + (n - Dd - Zz - Hh)] = a;
        }
    } else if (EP == MP_SC) {
        g_sc[((size_t)bz * Ss + m) * Ss + n] = acc * SCALING + p.aux[MPc - 1 + n - m];
    } else if (EP == MP_HR) {
        size_t o = ((size_t)(m * Bb + bz)) * Hh + n;
        g_hrh[o] = __float2half_rn(acc * g_r[o]);
    } else if (EP == MP_H2) {
        g_h2[(size_t)m * Dd + n] = silu(acc + p.bias[n] + g_hx[(size_t)m * Dd + n]);
    } else if (EP == MP_RELU) {
        g_inh[(size_t)m * II + n] = __float2half_rn(fmaxf(acc + p.bias[n], 0.f));
    } else {
        p.out[(size_t)m * Dd + n] = acc + p.bias[n] + g_ol[(size_t)m * Dd + n];
    }
}

// CTA 256x128, warp 64x64 (4m x 2n), K-chunk 64, cp.async-fed.
// TERMS=3: 2-stage (bf16 split, Ah*Bh+Al*Bh+Ah*Bl). TERMS=1: 3-stage (fp16, Ah*Bh).
template<int EP, int TERMS, typename ET>
__global__ void __launch_bounds__(256, 1) k_mgemm(TG p) {
    constexpr int TM = 256, TN = 128;
    constexpr int ASZ = TM * 128;
    constexpr int BSZ = TN * 128;
    constexpr int NA = (TERMS >= 2) ? 2 : 1;
    constexpr int NB = (TERMS == 3) ? 2 : 1;
    constexpr int STGB = NA * ASZ + NB * BSZ;
    constexpr int NSTG = (TERMS == 1) ? 3 : 2;
    constexpr int KT = 64;

    extern __shared__ char sm[];
    const unsigned sb = smem_u32(sm);

    const int t = threadIdx.x, lane = t & 31, wid = t >> 5;
    const int wm = wid & 3, wn = wid >> 2;
    const int g = lane >> 2, tig = lane & 3;
    const int bz = blockIdx.z;
    const int m0 = blockIdx.y * TM, n0 = blockIdx.x * TN;
    const ET* Ahp = (const ET*)p.Ah + (size_t)bz * (size_t)p.sA;
    const ET* Alp = (NA == 2) ? ((const ET*)p.Al + (size_t)bz * (size_t)p.sA) : nullptr;
    const ET* Bhp = (const ET*)p.Bh + (size_t)bz * (size_t)p.sB;
    const ET* Blp = (NB == 2) ? ((const ET*)p.Bl + (size_t)bz * (size_t)p.sB) : nullptr;
    const int K = p.K;
    const int nst = K / KT;
    const int Nv = p.Nv;

    const int matq = lane >> 3, r8 = lane & 7;
    const int amq = matq >> 1, bmq = matq & 1;
    unsigned aBase[4]; int aswz[4];
#pragma unroll
    for (int mi = 0; mi < 4; mi++) {
        int arow = wm * 64 + mi * 16 + (matq & 1) * 8 + r8;
        aBase[mi] = sb + arow * 128;
        aswz[mi] = arow & 7;
    }
    unsigned bBase[2][2]; int bswz[2][2];
#pragma unroll
    for (int nh = 0; nh < 2; nh++)
#pragma unroll
        for (int njp = 0; njp < 2; njp++) {
            int brow = wn * 64 + nh * 32 + njp * 16 + (matq >> 1) * 8 + r8;
            bBase[nh][njp] = sb + NA * ASZ + brow * 128;
            bswz[nh][njp] = brow & 7;
        }

    float acc[4][8][4];
#pragma unroll
    for (int i = 0; i < 4; i++)
#pragma unroll
        for (int j = 0; j < 8; j++)
#pragma unroll
            for (int r = 0; r < 4; r++) acc[i][j][r] = 0.f;

    auto CPA = [&](int k0, int buf) {
        unsigned ah = sb + buf * STGB, al = ah + ASZ;
#pragma unroll
        for (int j = 0; j < 8; j++) {
            int idx = t + 256 * j;
            int row = idx >> 3, q = idx & 7;
            unsigned off = row * 128 + ((q ^ (row & 7)) << 4);
            size_t go = (size_t)(m0 + row) * K + k0 + q * 8;
            cpa16(ah + off, Ahp + go);
            if (NA == 2) cpa16(al + off, Alp + go);
        }
    };
    auto CPB = [&](int k0, int buf) {
        unsigned bh = sb + buf * STGB + NA * ASZ, bl = bh + BSZ;
#pragma unroll
        for (int j = 0; j < 4; j++) {
            int idx = t + 256 * j;
            int row = idx >> 3, q = idx & 7;
            int rn = n0 + row; if (rn >= Nv) rn = Nv - 1;
            unsigned off = row * 128 + ((q ^ (row & 7)) << 4);
            size_t go = (size_t)rn * K + k0 + q * 8;
            cpa16(bh + off, Bhp + go);
            if (NB == 2) cpa16(bl + off, Blp + go);
        }
    };

    auto COMPUTE = [&](int buf) {
        const unsigned off = buf * STGB;
#pragma unroll
        for (int kk = 0; kk < 4; kk++) {
            unsigned Ah[4][4], Al[4][4];
#pragma unroll
            for (int mi = 0; mi < 4; mi++) {
                unsigned ao = off + (((kk * 2 + amq) ^ aswz[mi]) << 4);
                ldsm4(Ah[mi], aBase[mi] + ao);
                if (NA == 2) ldsm4(Al[mi], aBase[mi] + ao + ASZ);
            }
#pragma unroll
            for (int nh = 0; nh < 2; nh++) {
                unsigned Bh4[2][4], Bl4[2][4];
#pragma unroll
                for (int njp = 0; njp < 2; njp++) {
                    unsigned bo = off + (((kk * 2 + bmq) ^ bswz[nh][njp]) << 4);
                    ldsm4(Bh4[njp], bBase[nh][njp] + bo);
                    if (NB == 2) ldsm4(Bl4[njp], bBase[nh][njp] + bo + BSZ);
                }
#pragma unroll
                for (int nj = 0; nj < 4; nj++) {
                    int njp = nj >> 1, hi = (nj & 1) * 2;
                    unsigned bfh[2] = { Bh4[njp][hi], Bh4[njp][hi + 1] };
#pragma unroll
                    for (int mi = 0; mi < 4; mi++) {
                        float* c = acc[mi][nh * 4 + nj];
                        MMA<ET>::run(c, Ah[mi], bfh);
                        if (NA == 2) MMA<ET>::run(c, Al[mi], bfh);
                        if (NB == 2) {
                            unsigned bfl[2] = { Bl4[njp][hi], Bl4[njp][hi + 1] };
                            MMA<ET>::run(c, Ah[mi], bfl);
                        }
                    }
                }
            }
        }
    };

    if (NSTG == 3) {
        // 3-stage pipeline: groups committed every iteration (possibly empty);
        // at iter s, groups 0..s+1 committed; wait_group 1 => stage s complete.
        CPA(0, 0); CPB(0, 0); CP_COMMIT;
        if (nst > 1) { CPA(KT, 1); CPB(KT, 1); }
        CP_COMMIT;
        for (int s = 0; s < nst; s++) {
            CP_WAIT1;
            __syncthreads();      // stage s visible; all threads done COMPUTE(s-1)
            if (s + 2 < nst) { CPA((s + 2) * KT, (s + 2) % 3); CPB((s + 2) * KT, (s + 2) % 3); }
            CP_COMMIT;
            COMPUTE(s % 3);
        }
    } else {
        CPA(0, 0); CPB(0, 0); CP_COMMIT;
        CP_WAIT0;
        __syncthreads();
        for (int s = 0; s < nst; s++) {
            if (s + 1 < nst) { CPA((s + 1) * KT, (s + 1) & 1); CPB((s + 1) * KT, (s + 1) & 1); CP_COMMIT; }
            COMPUTE(s & 1);
            if (s + 1 < nst) CP_WAIT0;
            __syncthreads();
        }
    }
    __syncthreads();

#pragma unroll
    for (int mi = 0; mi < 4; mi++)
#pragma unroll
        for (int ni = 0; ni < 8; ni++) {
            int row0 = m0 + wm * 64 + mi * 16 + g;
            int col0 = n0 + wn * 64 + ni * 8 + 2 * tig;
            float* c = acc[mi][ni];
            if (col0 < Nv)     epiM<EP>(p, bz, row0,     col0,     c[0]);
            if (col0 + 1 < Nv) epiM<EP>(p, bz, row0,     col0 + 1, c[1]);
            if (col0 < Nv)     epiM<EP>(p, bz, row0 + 8, col0,     c[2]);
            if (col0 + 1 < Nv) epiM<EP>(p, bz, row0 + 8, col0 + 1, c[3]);
        }
}

// ---------------- launch ----------------
constexpr int SMM3 = 2 * (2 * 256 * 128 + 2 * 128 * 128);  // 196608 (2-stage, 3-term)
constexpr int SMM1 = 3 * (1 * 256 * 128 + 1 * 128 * 128);  // 147456 (3-stage, 1-term)
typedef __nv_bfloat16 BF;
typedef __half HF;

extern "C" void kernel_launch(void* const* d_in, const int* in_sizes, int n_in,
                              void* d_out, int out_size) {
    (void)in_sizes; (void)n_in; (void)out_size;
    const float* x    = (const float*)d_in[0];
    const float* ln_s = (const float*)d_in[1];
    const float* ln_b = (const float*)d_in[2];
    const float* v_w  = (const float*)d_in[3];
    const float* v_b  = (const float*)d_in[4];
    const float* mx_w = (const float*)d_in[5];
    const float* mx_b = (const float*)d_in[6];
    const float* h_w  = (const float*)d_in[7];
    const float* h_b  = (const float*)d_in[8];
    const float* gamma= (const float*)d_in[9];
    const float* beta = (const float*)d_in[10];
    const float* rel  = (const float*)d_in[11];
    const float* e_d  = (const float*)d_in[12];
    const float* e_a  = (const float*)d_in[13];
    const float* e_b  = (const float*)d_in[14];
    const float* e_g  = (const float*)d_in[15];
    const float* e_o  = (const float*)d_in[16];
    const float* f_s  = (const float*)d_in[17];
    const float* f_b  = (const float*)d_in[18];
    const float* w1   = (const float*)d_in[19];
    const float* b1   = (const float*)d_in[20];
    const float* w2   = (const float*)d_in[21];
    const float* b2   = (const float*)d_in[22];

    HF *p_xnh, *p_mxh, *p_sch, *p_hrh, *p_olh, *p_inh;
    HF *p_vh, *p_wvh, *p_whh, *p_w1h, *p_w2h, *p_wmh;
    BF *p_qh, *p_ql, *p_kh, *p_kl;
    cudaGetSymbolAddress((void**)&p_xnh, g_xnh);
    cudaGetSymbolAddress((void**)&p_mxh, g_mxh);
    cudaGetSymbolAddress((void**)&p_sch, g_sch);
    cudaGetSymbolAddress((void**)&p_hrh, g_hrh);
    cudaGetSymbolAddress((void**)&p_olh, g_olh);
    cudaGetSymbolAddress((void**)&p_inh, g_inh);
    cudaGetSymbolAddress((void**)&p_vh,  g_vh);
    cudaGetSymbolAddress((void**)&p_wvh, g_wvh);
    cudaGetSymbolAddress((void**)&p_whh, g_whh);
    cudaGetSymbolAddress((void**)&p_w1h, g_w1h);
    cudaGetSymbolAddress((void**)&p_w2h, g_w2h);
    cudaGetSymbolAddress((void**)&p_wmh, g_wmh);
    cudaGetSymbolAddress((void**)&p_qh,  g_qh);
    cudaGetSymbolAddress((void**)&p_ql,  g_ql);
    cudaGetSymbolAddress((void**)&p_kh,  g_kh);
    cudaGetSymbolAddress((void**)&p_kl,  g_kl);

    cudaFuncSetAttribute(k_mgemm<MP_V,    1, HF>, cudaFuncAttributeMaxDynamicSharedMemorySize, SMM1);
    cudaFuncSetAttribute(k_mgemm<MP_BASE, 1, HF>, cudaFuncAttributeMaxDynamicSharedMemorySize, SMM1);
    cudaFuncSetAttribute(k_mgemm<MP_SC,   3, BF>, cudaFuncAttributeMaxDynamicSharedMemorySize, SMM3);
    cudaFuncSetAttribute(k_mgemm<MP_HR,   1, HF>, cudaFuncAttributeMaxDynamicSharedMemorySize, SMM1);
    cudaFuncSetAttribute(k_mgemm<MP_H2,   1, HF>, cudaFuncAttributeMaxDynamicSharedMemorySize, SMM1);
    cudaFuncSetAttribute(k_mgemm<MP_RELU, 1, HF>, cudaFuncAttributeMaxDynamicSharedMemorySize, SMM1);
    cudaFuncSetAttribute(k_mgemm<MP_FIN,  1, HF>, cudaFuncAttributeMaxDynamicSharedMemorySize, SMM1);

    // weight prep
    k_wt<HF, false><<<dim3(Hh / 32, Dd / 32), 256>>>(v_w, p_wvh, nullptr, Dd, Hh);
    k_wt<HF, false><<<dim3(NMX / 32, Dd / 32), 256>>>(mx_w, p_wmh, nullptr, Dd, NMX);
    k_wt<HF, false><<<dim3(Dd / 32, Hh / 32), 256>>>(h_w, p_whh, nullptr, Hh, Dd);
    k_wt<HF, false><<<dim3(II / 32, Dd / 32), 256>>>(w1, p_w1h, nullptr, Dd, II);
    k_wt<HF, false><<<dim3(Dd / 32, II / 32), 256>>>(w2, p_w2h, nullptr, II, Dd);

    k_ln1<<<SB, 256>>>(x, ln_s, ln_b);
    k_ema<<<(Bb * Dd) / 16, 256>>>(e_d, e_a, e_b, e_g, e_o);

    TG p;
    // v = silu(xn @ v_w + v_b) -> v^T fp16  (1-term, 3-stage)
    p = {p_xnh, nullptr, p_wvh, nullptr, v_b, nullptr, nullptr, nullptr, Dd, Hh, 0, 0};
    k_mgemm<MP_V, 1, HF><<<dim3(Hh / 128, SB / 256, 1), 256, SMM1>>>(p);
    // base = mx @ mx_w + mx_b -> u,(q,k),r,hx  (1-term, 3-stage)
    p = {p_mxh, nullptr, p_wmh, nullptr, mx_b, gamma, beta, nullptr, Dd, NMX, 0, 0};
    k_mgemm<MP_BASE, 1, HF><<<dim3(NMX / 128, SB / 256, 1), 256, SMM1>>>(p);
    // scores = scaling * q @ k^T + relpos  (3-term bf16, 2-stage, batched)
    p = {p_qh, p_ql, p_kh, p_kl, nullptr, rel, nullptr, nullptr, Zz, Ss, (long long)Ss * Zz, (long long)Ss * Zz};
    k_mgemm<MP_SC, 3, BF><<<dim3(Ss / 128, Ss / 256, Bb), 256, SMM3>>>(p);
    k_softmax<<<Bb * Ss, 256>>>();
    // hr = (attn @ v) * r  (1-term, 3-stage, batched, fused)
    p = {p_sch, nullptr, p_vh, nullptr, nullptr, nullptr, nullptr, nullptr, Ss, Hh, (long long)Ss * Ss, (long long)Hh * Ss};
    k_mgemm<MP_HR, 1, HF><<<dim3(Hh / 128, Ss / 256, Bb), 256, SMM1>>>(p);
    // h2 = silu(hx + hr @ h_w + h_b)  (1-term, 3-stage)
    p = {p_hrh, nullptr, p_whh, nullptr, h_b, nullptr, nullptr, nullptr, Hh, Dd, 0, 0};
    k_mgemm<MP_H2, 1, HF><<<dim3(Dd / 128, SB / 256, 1), 256, SMM1>>>(p);
    k_gateln<<<SB, 256>>>(f_s, f_b);
    // FFN  (1-term, 3-stage)
    p = {p_olh, nullptr, p_w1h, nullptr, b1, nullptr, nullptr, nullptr, Dd, II, 0, 0};
    k_mgemm<MP_RELU, 1, HF><<<dim3(II / 128, SB / 256, 1), 256, SMM1>>>(p);
    p = {p_inh, nullptr, p_w2h, nullptr, b2, nullptr, nullptr, (float*)d_out, II, Dd, 0, 0};
    k_mgemm<MP_FIN, 1, HF><<<dim3(Dd / 128, SB / 256, 1), 256, SMM1>>>(p);
}

// round 17
// speedup vs baseline: 2.1716x; 1.2594x over previous
#include <cuda_runtime.h>
#include <cuda_bf16.h>
#include <cuda_fp16.h>
#include <math.h>

#define DEVFN __device__ __forceinline__
#define DG __device__ __align__(128)

constexpr int Bb = 8, Ss = 2048, Dd = 1024, Zz = 128, Nn = 16, Hh = 2048, II = 4096, MPc = 2048;
constexpr int SB = Ss * Bb;
constexpr int NMX = Dd + Zz + Hh + Dd;  // 4224
constexpr float EPS = 1e-3f;
constexpr float SCALING = 0.08838834764831843f;

// ---------------- scratch ----------------
DG float g_u [(size_t)SB * Dd];
DG float g_hx[(size_t)SB * Dd];
DG float g_r [(size_t)SB * Hh];
DG float g_sc[(size_t)Bb * Ss * Ss];
DG float g_h2[(size_t)SB * Dd];
DG float g_ol[(size_t)SB * Dd];
// fp16 A operands
DG __half g_xnh[(size_t)SB * Dd];
DG __half g_mxh[(size_t)SB * Dd];
DG __half g_sch[(size_t)Bb * Ss * Ss];
DG __half g_hrh[(size_t)SB * Hh];
DG __half g_olh[(size_t)SB * Dd];
DG __half g_inh[(size_t)SB * II];
// fp16 B operands
DG __half g_vh [(size_t)Bb * Hh * Ss];
DG __half g_wvh[(size_t)Hh * Dd];
DG __half g_whh[(size_t)Dd * Hh];
DG __half g_w1h[(size_t)II * Dd];
DG __half g_w2h[(size_t)Dd * II];
DG __half g_wmh[(size_t)NMX * Dd];
// bf16 split operands (3-term scores GEMM)
DG __nv_bfloat16 g_qh[(size_t)Bb * Ss * Zz], g_ql[(size_t)Bb * Ss * Zz];
DG __nv_bfloat16 g_kh[(size_t)Bb * Ss * Zz], g_kl[(size_t)Bb * Ss * Zz];

// ---------------- helpers ----------------
DEVFN float sigm(float x) { return 1.f / (1.f + __expf(-x)); }
DEVFN float silu(float x) { return x / (1.f + __expf(-x)); }
DEVFN void splitB(__nv_bfloat16* oh, __nv_bfloat16* ol, size_t i, float v) {
    __nv_bfloat16 h = __float2bfloat16(v);
    oh[i] = h;
    ol[i] = __float2bfloat16(v - __bfloat162float(h));
}
DEVFN float warpSum(float v) {
#pragma unroll
    for (int o = 16; o; o >>= 1) v += __shfl_xor_sync(~0u, v, o);
    return v;
}
DEVFN float warpMax(float v) {
#pragma unroll
    for (int o = 16; o; o >>= 1) v = fmaxf(v, __shfl_xor_sync(~0u, v, o));
    return v;
}
DEVFN void blockSum2(float& a, float& b) {
    __shared__ float sa[8], sb_[8];
    float wa = warpSum(a), wb = warpSum(b);
    if ((threadIdx.x & 31) == 0) { sa[threadIdx.x >> 5] = wa; sb_[threadIdx.x >> 5] = wb; }
    __syncthreads();
    a = b = 0.f;
#pragma unroll
    for (int i = 0; i < 8; i++) { a += sa[i]; b += sb_[i]; }
    __syncthreads();
}
DEVFN float blockSum1(float v) {
    __shared__ float s[8];
    float w = warpSum(v);
    if ((threadIdx.x & 31) == 0) s[threadIdx.x >> 5] = w;
    __syncthreads();
    float r = 0.f;
#pragma unroll
    for (int i = 0; i < 8; i++) r += s[i];
    __syncthreads();
    return r;
}
DEVFN float blockMax1(float v) {
    __shared__ float s[8];
    float w = warpMax(v);
    if ((threadIdx.x & 31) == 0) s[threadIdx.x >> 5] = w;
    __syncthreads();
    float r = s[0];
#pragma unroll
    for (int i = 1; i < 8; i++) r = fmaxf(r, s[i]);
    __syncthreads();
    return r;
}

template<typename ET> struct MMA;
template<> struct MMA<__nv_bfloat16> {
    static DEVFN void run(float* c, const unsigned* a, const unsigned* b) {
        asm volatile(
            "mma.sync.aligned.m16n8k16.row.col.f32.bf16.bf16.f32 "
            "{%0,%1,%2,%3},{%4,%5,%6,%7},{%8,%9},{%0,%1,%2,%3};"
            : "+f"(c[0]), "+f"(c[1]), "+f"(c[2]), "+f"(c[3])
            : "r"(a[0]), "r"(a[1]), "r"(a[2]), "r"(a[3]), "r"(b[0]), "r"(b[1]));
    }
};
template<> struct MMA<__half> {
    static DEVFN void run(float* c, const unsigned* a, const unsigned* b) {
        asm volatile(
            "mma.sync.aligned.m16n8k16.row.col.f32.f16.f16.f32 "
            "{%0,%1,%2,%3},{%4,%5,%6,%7},{%8,%9},{%0,%1,%2,%3};"
            : "+f"(c[0]), "+f"(c[1]), "+f"(c[2]), "+f"(c[3])
            : "r"(a[0]), "r"(a[1]), "r"(a[2]), "r"(a[3]), "r"(b[0]), "r"(b[1]));
    }
};

DEVFN void ldsm4(unsigned* r, unsigned addr) {
    asm volatile("ldmatrix.sync.aligned.m8n8.x4.shared.b16 {%0,%1,%2,%3}, [%4];"
                 : "=r"(r[0]), "=r"(r[1]), "=r"(r[2]), "=r"(r[3]) : "r"(addr));
}
DEVFN void ldsm2(unsigned* r, unsigned addr) {
    asm volatile("ldmatrix.sync.aligned.m8n8.x2.shared.b16 {%0,%1}, [%2];"
                 : "=r"(r[0]), "=r"(r[1]) : "r"(addr));
}
DEVFN void cpa16(unsigned dst, const void* src) {
    asm volatile("cp.async.cg.shared.global [%0], [%1], 16;" :: "r"(dst), "l"(src) : "memory");
}
#define CP_COMMIT asm volatile("cp.async.commit_group;" ::: "memory")
#define CP_WAIT0  asm volatile("cp.async.wait_group 0;" ::: "memory")
DEVFN unsigned smem_u32(const void* p) {
    unsigned a;
    asm("{ .reg .u64 t; cvta.to.shared.u64 t, %1; cvt.u32.u64 %0, t; }" : "=r"(a) : "l"(p));
    return a;
}

// ---------------- elementwise ----------------
__global__ __launch_bounds__(256) void k_ln1(const float* __restrict__ x,
                                             const float* __restrict__ sc,
                                             const float* __restrict__ bi) {
    int m = blockIdx.x, b = m / Ss, s = m % Ss, t = threadIdx.x;
    const float* xr = x + (size_t)m * Dd;
    float v[4], su = 0.f, sq = 0.f;
#pragma unroll
    for (int i = 0; i < 4; i++) { float f = xr[t + 256 * i]; v[i] = f; su += f; sq += f * f; }
    blockSum2(su, sq);
    float mu = su * (1.f / Dd), inv = rsqrtf(sq * (1.f / Dd) - mu * mu + EPS);
    size_t base = (size_t)(s * Bb + b) * Dd;
#pragma unroll
    for (int i = 0; i < 4; i++) {
        int d = t + 256 * i;
        float val = (v[i] - mu) * inv * sc[d] + bi[d];
        g_xnh[base + d] = __float2half_rn(val);
    }
}

__global__ __launch_bounds__(256) void k_ema(const float* __restrict__ de, const float* __restrict__ al,
                                             const float* __restrict__ be, const float* __restrict__ ga,
                                             const float* __restrict__ om) {
    int t = threadIdx.x, lane = t & 15;
    int P = blockIdx.x * 16 + (t >> 4), b = P / Dd, d = P % Dd;
    int pi = d * Nn + lane;
    float p = sigm(de[pi]);
    float q = 1.f - p * sigm(al[pi]);
    float coef = p * be[pi] * ga[pi] * 0.25f;
    float w = om[d];
    const __half* xp = g_xnh + (size_t)b * Dd + d;
    size_t obase = (size_t)b * Dd + d;
    float s = 0.f;
    for (int l = 0; l < Ss; l++) {
        float xv = __half2float(xp[(size_t)l * (Bb * Dd)]);
        s = fmaf(q, s, xv);
        float r = coef * s;
        r += __shfl_xor_sync(~0u, r, 1);
        r += __shfl_xor_sync(~0u, r, 2);
        r += __shfl_xor_sync(~0u, r, 4);
        r += __shfl_xor_sync(~0u, r, 8);
        if (lane == 0)
            g_mxh[obase + (size_t)l * (Bb * Dd)] = __float2half_rn(silu(r + xv * w));
    }
}

__global__ __launch_bounds__(256) void k_softmax() {
    size_t rbase = (size_t)blockIdx.x * Ss;
    const float* rp = g_sc + rbase;
    int t = threadIdx.x;
    float v[8], mx = -1e30f;
#pragma unroll
    for (int i = 0; i < 8; i++) { v[i] = rp[t + 256 * i]; mx = fmaxf(mx, v[i]); }
    mx = blockMax1(mx);
    float su = 0.f;
#pragma unroll
    for (int i = 0; i < 8; i++) { v[i] = __expf(v[i] - mx); su += v[i]; }
    su = blockSum1(su);
    float inv = 1.f / su;
#pragma unroll
    for (int i = 0; i < 8; i++)
        g_sch[rbase + t + 256 * i] = __float2half_rn(v[i] * inv);
}

__global__ __launch_bounds__(256) void k_gateln(const float* __restrict__ sc,
                                                const float* __restrict__ bi) {
    int m = blockIdx.x, s = m >> 3, b = m & 7, t = threadIdx.x;
    size_t base = (size_t)m * Dd;
    float g[4], su = 0.f, sq = 0.f;
#pragma unroll
    for (int i = 0; i < 4; i++) {
        int d = t + 256 * i;
        float xn = __half2float(g_xnh[base + d]);
        float val = xn + g_u[base + d] * (g_h2[base + d] - xn);
        g[i] = val; su += val; sq += val * val;
    }
    blockSum2(su, sq);
    float mu = su * (1.f / Dd), inv = rsqrtf(sq * (1.f / Dd) - mu * mu + EPS);
    size_t ob = ((size_t)b * Ss + s) * Dd;
#pragma unroll
    for (int i = 0; i < 4; i++) {
        int d = t + 256 * i;
        float val = (g[i] - mu) * inv * sc[d] + bi[d];
        g_ol[ob + d] = val;
        g_olh[ob + d] = __float2half_rn(val);
    }
}

template<typename T, bool LO>
__global__ __launch_bounds__(256) void k_wt(const float* __restrict__ W,
                                            T* __restrict__ oh,
                                            T* __restrict__ ol, int K, int N) {
    __shared__ float tl[32][33];
    int n0 = blockIdx.x * 32, k0 = blockIdx.y * 32;
    int tx = threadIdx.x & 31, ty = threadIdx.x >> 5;
#pragma unroll
    for (int i = 0; i < 4; i++) tl[ty + i * 8][tx] = W[(size_t)(k0 + ty + i * 8) * N + n0 + tx];
    __syncthreads();
#pragma unroll
    for (int i = 0; i < 4; i++) {
        int ny = ty + i * 8;
        float v = tl[tx][ny];
        size_t o = (size_t)(n0 + ny) * K + k0 + tx;
        T h = (T)v;
        oh[o] = h;
        if (LO) ol[o] = (T)(v - (float)h);
    }
}

// ================= mma.sync GEMM =================
// TERMS=1: TM=128,TN=128, warp 64x32 (2x4), 2-stage 64KB, occupancy 2, fp16.
// TERMS=3: TM=256,TN=128, warp 64x64 (4x2), 2-stage 196KB, occupancy 1, bf16 split.
struct TG {
    const void* Ah; const void* Al;
    const void* Bh; const void* Bl;
    const float* bias; const float* aux; const float* aux2;
    float* out;
    int K, Nv;
    long long sA, sB;
};

enum { MP_V = 0, MP_BASE, MP_SC, MP_HR, MP_H2, MP_RELU, MP_FIN };

template<int EP>
DEVFN void epiM(const TG& p, int bz, int m, int n, float acc) {
    if (EP == MP_V) {
        float v = silu(acc + p.bias[n]);
        int s = m >> 3, b = m & 7;
        g_vh[((size_t)(b * Hh + n)) * Ss + s] = __float2half_rn(v);
    } else if (EP == MP_BASE) {
        float a = acc + p.bias[n];
        if (n < Dd) {
            g_u[(size_t)m * Dd + n] = sigm(a);
        } else if (n < Dd + Zz) {
            float z = silu(a); int zi = n - Dd;
            int s = m >> 3, b = m & 7;
            size_t o = ((size_t)(b * Ss + s)) * Zz + zi;
            splitB(g_qh, g_ql, o, z * p.aux[zi] + p.aux2[zi]);
            splitB(g_kh, g_kl, o, z * p.aux[Zz + zi] + p.aux2[Zz + zi]);
        } else if (n < Dd + Zz + Hh) {
            g_r[(size_t)m * Hh + (n - Dd - Zz)] = silu(a);
        } else {
            g_hx[(size_t)m * Dd + (n - Dd - Zz - Hh)] = a;
        }
    } else if (EP == MP_SC) {
        g_sc[((size_t)bz * Ss + m) * Ss + n] = acc * SCALING + p.aux[MPc - 1 + n - m];
    } else if (EP == MP_HR) {
        size_t o = ((size_t)(m * Bb + bz)) * Hh + n;
        g_hrh[o] = __float2half_rn(acc * g_r[o]);
    } else if (EP == MP_H2) {
        g_h2[(size_t)m * Dd + n] = silu(acc + p.bias[n] + g_hx[(size_t)m * Dd + n]);
    } else if (EP == MP_RELU) {
        g_inh[(size_t)m * II + n] = __float2half_rn(fmaxf(acc + p.bias[n], 0.f));
    } else {
        p.out[(size_t)m * Dd + n] = acc + p.bias[n] + g_ol[(size_t)m * Dd + n];
    }
}

template<int EP, int TERMS, typename ET>
__global__ void __launch_bounds__(256, (TERMS == 1) ? 2 : 1) k_mgemm(TG p) {
    constexpr int TM = (TERMS == 1) ? 128 : 256;
    constexpr int TN = 128;
    constexpr int WNT = (TERMS == 1) ? 32 : 64;   // warp N tile
    constexpr int NWM = TM / 64;                  // warps along M
    constexpr int NH = WNT / 32;                  // 32-col groups per warp
    constexpr int ASZ = TM * 128;
    constexpr int BSZ = TN * 128;
    constexpr int NA = (TERMS >= 2) ? 2 : 1;
    constexpr int NB = (TERMS == 3) ? 2 : 1;
    constexpr int STGB = NA * ASZ + NB * BSZ;
    constexpr int KT = 64;
    constexpr int IA = TM / 32;                   // A cp.async per thread
    constexpr int IB = TN / 32;

    extern __shared__ char sm[];
    const unsigned sb = smem_u32(sm);

    const int t = threadIdx.x, lane = t & 31, wid = t >> 5;
    const int wm = wid % NWM, wn = wid / NWM;
    const int g = lane >> 2, tig = lane & 3;
    const int bz = blockIdx.z;
    const int m0 = blockIdx.y * TM, n0 = blockIdx.x * TN;
    const ET* Ahp = (const ET*)p.Ah + (size_t)bz * (size_t)p.sA;
    const ET* Alp = (NA == 2) ? ((const ET*)p.Al + (size_t)bz * (size_t)p.sA) : nullptr;
    const ET* Bhp = (const ET*)p.Bh + (size_t)bz * (size_t)p.sB;
    const ET* Blp = (NB == 2) ? ((const ET*)p.Bl + (size_t)bz * (size_t)p.sB) : nullptr;
    const int K = p.K;
    const int nst = K / KT;
    const int Nv = p.Nv;

    const int matq = lane >> 3, r8 = lane & 7;
    const int amq = matq >> 1, bmq = matq & 1;
    unsigned aBase[4]; int aswz[4];
#pragma unroll
    for (int mi = 0; mi < 4; mi++) {
        int arow = wm * 64 + mi * 16 + (matq & 1) * 8 + r8;
        aBase[mi] = sb + arow * 128;
        aswz[mi] = arow & 7;
    }
    unsigned bBase[NH][2]; int bswz[NH][2];
#pragma unroll
    for (int nh = 0; nh < NH; nh++)
#pragma unroll
        for (int njp = 0; njp < 2; njp++) {
            int brow = wn * WNT + nh * 32 + njp * 16 + (matq >> 1) * 8 + r8;
            bBase[nh][njp] = sb + NA * ASZ + brow * 128;
            bswz[nh][njp] = brow & 7;
        }

    float acc[4][NH * 4][4];
#pragma unroll
    for (int i = 0; i < 4; i++)
#pragma unroll
        for (int j = 0; j < NH * 4; j++)
#pragma unroll
            for (int r = 0; r < 4; r++) acc[i][j][r] = 0.f;

    auto CPA = [&](int k0, int buf) {
        unsigned ah = sb + buf * STGB, al = ah + ASZ;
#pragma unroll
        for (int j = 0; j < IA; j++) {
            int idx = t + 256 * j;
            int row = idx >> 3, q = idx & 7;
            unsigned off = row * 128 + ((q ^ (row & 7)) << 4);
            size_t go = (size_t)(m0 + row) * K + k0 + q * 8;
            cpa16(ah + off, Ahp + go);
            if (NA == 2) cpa16(al + off, Alp + go);
        }
    };
    auto CPB = [&](int k0, int buf) {
        unsigned bh = sb + buf * STGB + NA * ASZ, bl = bh + BSZ;
#pragma unroll
        for (int j = 0; j < IB; j++) {
            int idx = t + 256 * j;
            int row = idx >> 3, q = idx & 7;
            int rn = n0 + row; if (rn >= Nv) rn = Nv - 1;
            unsigned off = row * 128 + ((q ^ (row & 7)) << 4);
            size_t go = (size_t)rn * K + k0 + q * 8;
            cpa16(bh + off, Bhp + go);
            if (NB == 2) cpa16(bl + off, Blp + go);
        }
    };

    auto COMPUTE = [&](int buf) {
        const unsigned off = buf * STGB;
#pragma unroll
        for (int kk = 0; kk < 4; kk++) {
            unsigned Ah[4][4], Al[4][4];
#pragma unroll
            for (int mi = 0; mi < 4; mi++) {
                unsigned ao = off + (((kk * 2 + amq) ^ aswz[mi]) << 4);
                ldsm4(Ah[mi], aBase[mi] + ao);
                if (NA == 2) ldsm4(Al[mi], aBase[mi] + ao + ASZ);
            }
#pragma unroll
            for (int nh = 0; nh < NH; nh++) {
                unsigned Bh4[2][4], Bl4[2][4];
#pragma unroll
                for (int njp = 0; njp < 2; njp++) {
                    unsigned bo = off + (((kk * 2 + bmq) ^ bswz[nh][njp]) << 4);
                    ldsm4(Bh4[njp], bBase[nh][njp] + bo);
                    if (NB == 2) ldsm4(Bl4[njp], bBase[nh][njp] + bo + BSZ);
                }
#pragma unroll
                for (int nj = 0; nj < 4; nj++) {
                    int njp = nj >> 1, hi = (nj & 1) * 2;
                    unsigned bfh[2] = { Bh4[njp][hi], Bh4[njp][hi + 1] };
#pragma unroll
                    for (int mi = 0; mi < 4; mi++) {
                        float* c = acc[mi][nh * 4 + nj];
                        MMA<ET>::run(c, Ah[mi], bfh);
                        if (NA == 2) MMA<ET>::run(c, Al[mi], bfh);
                        if (NB == 2) {
                            unsigned bfl[2] = { Bl4[njp][hi], Bl4[njp][hi + 1] };
                            MMA<ET>::run(c, Ah[mi], bfl);
                        }
                    }
                }
            }
        }
    };

    CPA(0, 0); CPB(0, 0); CP_COMMIT;
    CP_WAIT0;
    __syncthreads();

    for (int s = 0; s < nst; s++) {
        if (s + 1 < nst) { CPA((s + 1) * KT, (s + 1) & 1); CPB((s + 1) * KT, (s + 1) & 1); CP_COMMIT; }
        COMPUTE(s & 1);
        if (s + 1 < nst) CP_WAIT0;
        __syncthreads();
    }

#pragma unroll
    for (int mi = 0; mi < 4; mi++)
#pragma unroll
        for (int ni = 0; ni < NH * 4; ni++) {
            int row0 = m0 + wm * 64 + mi * 16 + g;
            int col0 = n0 + wn * WNT + ni * 8 + 2 * tig;
            float* c = acc[mi][ni];
            if (col0 < Nv)     epiM<EP>(p, bz, row0,     col0,     c[0]);
            if (col0 + 1 < Nv) epiM<EP>(p, bz, row0,     col0 + 1, c[1]);
            if (col0 < Nv)     epiM<EP>(p, bz, row0 + 8, col0,     c[2]);
            if (col0 + 1 < Nv) epiM<EP>(p, bz, row0 + 8, col0 + 1, c[3]);
        }
}

// ---------------- launch ----------------
constexpr int SMM3 = 2 * (2 * 256 * 128 + 2 * 128 * 128);  // 196608 (3-term, occ1)
constexpr int SMM1 = 2 * (1 * 128 * 128 + 1 * 128 * 128);  // 65536  (1-term, occ2)
typedef __nv_bfloat16 BF;
typedef __half HF;

extern "C" void kernel_launch(void* const* d_in, const int* in_sizes, int n_in,
                              void* d_out, int out_size) {
    (void)in_sizes; (void)n_in; (void)out_size;
    const float* x    = (const float*)d_in[0];
    const float* ln_s = (const float*)d_in[1];
    const float* ln_b = (const float*)d_in[2];
    const float* v_w  = (const float*)d_in[3];
    const float* v_b  = (const float*)d_in[4];
    const float* mx_w = (const float*)d_in[5];
    const float* mx_b = (const float*)d_in[6];
    const float* h_w  = (const float*)d_in[7];
    const float* h_b  = (const float*)d_in[8];
    const float* gamma= (const float*)d_in[9];
    const float* beta = (const float*)d_in[10];
    const float* rel  = (const float*)d_in[11];
    const float* e_d  = (const float*)d_in[12];
    const float* e_a  = (const float*)d_in[13];
    const float* e_b  = (const float*)d_in[14];
    const float* e_g  = (const float*)d_in[15];
    const float* e_o  = (const float*)d_in[16];
    const float* f_s  = (const float*)d_in[17];
    const float* f_b  = (const float*)d_in[18];
    const float* w1   = (const float*)d_in[19];
    const float* b1   = (const float*)d_in[20];
    const float* w2   = (const float*)d_in[21];
    const float* b2   = (const float*)d_in[22];

    HF *p_xnh, *p_mxh, *p_sch, *p_hrh, *p_olh, *p_inh;
    HF *p_vh, *p_wvh, *p_whh, *p_w1h, *p_w2h, *p_wmh;
    BF *p_qh, *p_ql, *p_kh, *p_kl;
    cudaGetSymbolAddress((void**)&p_xnh, g_xnh);
    cudaGetSymbolAddress((void**)&p_mxh, g_mxh);
    cudaGetSymbolAddress((void**)&p_sch, g_sch);
    cudaGetSymbolAddress((void**)&p_hrh, g_hrh);
    cudaGetSymbolAddress((void**)&p_olh, g_olh);
    cudaGetSymbolAddress((void**)&p_inh, g_inh);
    cudaGetSymbolAddress((void**)&p_vh,  g_vh);
    cudaGetSymbolAddress((void**)&p_wvh, g_wvh);
    cudaGetSymbolAddress((void**)&p_whh, g_whh);
    cudaGetSymbolAddress((void**)&p_w1h, g_w1h);
    cudaGetSymbolAddress((void**)&p_w2h, g_w2h);
    cudaGetSymbolAddress((void**)&p_wmh, g_wmh);
    cudaGetSymbolAddress((void**)&p_qh,  g_qh);
    cudaGetSymbolAddress((void**)&p_ql,  g_ql);
    cudaGetSymbolAddress((void**)&p_kh,  g_kh);
    cudaGetSymbolAddress((void**)&p_kl,  g_kl);

    cudaFuncSetAttribute(k_mgemm<MP_V,    1, HF>, cudaFuncAttributeMaxDynamicSharedMemorySize, SMM1);
    cudaFuncSetAttribute(k_mgemm<MP_BASE, 1, HF>, cudaFuncAttributeMaxDynamicSharedMemorySize, SMM1);
    cudaFuncSetAttribute(k_mgemm<MP_SC,   3, BF>, cudaFuncAttributeMaxDynamicSharedMemorySize, SMM3);
    cudaFuncSetAttribute(k_mgemm<MP_HR,   1, HF>, cudaFuncAttributeMaxDynamicSharedMemorySize, SMM1);
    cudaFuncSetAttribute(k_mgemm<MP_H2,   1, HF>, cudaFuncAttributeMaxDynamicSharedMemorySize, SMM1);
    cudaFuncSetAttribute(k_mgemm<MP_RELU, 1, HF>, cudaFuncAttributeMaxDynamicSharedMemorySize, SMM1);
    cudaFuncSetAttribute(k_mgemm<MP_FIN,  1, HF>, cudaFuncAttributeMaxDynamicSharedMemorySize, SMM1);

    // weight prep
    k_wt<HF, false><<<dim3(Hh / 32, Dd / 32), 256>>>(v_w, p_wvh, nullptr, Dd, Hh);
    k_wt<HF, false><<<dim3(NMX / 32, Dd / 32), 256>>>(mx_w, p_wmh, nullptr, Dd, NMX);
    k_wt<HF, false><<<dim3(Dd / 32, Hh / 32), 256>>>(h_w, p_whh, nullptr, Hh, Dd);
    k_wt<HF, false><<<dim3(II / 32, Dd / 32), 256>>>(w1, p_w1h, nullptr, Dd, II);
    k_wt<HF, false><<<dim3(Dd / 32, II / 32), 256>>>(w2, p_w2h, nullptr, II, Dd);

    k_ln1<<<SB, 256>>>(x, ln_s, ln_b);
    k_ema<<<(Bb * Dd) / 16, 256>>>(e_d, e_a, e_b, e_g, e_o);

    TG p;
    // v = silu(xn @ v_w + v_b) -> v^T fp16  (1-term, occ2)
    p = {p_xnh, nullptr, p_wvh, nullptr, v_b, nullptr, nullptr, nullptr, Dd, Hh, 0, 0};
    k_mgemm<MP_V, 1, HF><<<dim3(Hh / 128, SB / 128, 1), 256, SMM1>>>(p);
    // base = mx @ mx_w + mx_b -> u,(q,k),r,hx  (1-term, occ2)
    p = {p_mxh, nullptr, p_wmh, nullptr, mx_b, gamma, beta, nullptr, Dd, NMX, 0, 0};
    k_mgemm<MP_BASE, 1, HF><<<dim3(NMX / 128, SB / 128, 1), 256, SMM1>>>(p);
    // scores = scaling * q @ k^T + relpos  (3-term bf16, occ1, batched)
    p = {p_qh, p_ql, p_kh, p_kl, nullptr, rel, nullptr, nullptr, Zz, Ss, (long long)Ss * Zz, (long long)Ss * Zz};
    k_mgemm<MP_SC, 3, BF><<<dim3(Ss / 128, Ss / 256, Bb), 256, SMM3>>>(p);
    k_softmax<<<Bb * Ss, 256>>>();
    // hr = (attn @ v) * r  (1-term, occ2, batched, fused)
    p = {p_sch, nullptr, p_vh, nullptr, nullptr, nullptr, nullptr, nullptr, Ss, Hh, (long long)Ss * Ss, (long long)Hh * Ss};
    k_mgemm<MP_HR, 1, HF><<<dim3(Hh / 128, Ss / 128, Bb), 256, SMM1>>>(p);
    // h2 = silu(hx + hr @ h_w + h_b)  (1-term, occ2)
    p = {p_hrh, nullptr, p_whh, nullptr, h_b, nullptr, nullptr, nullptr, Hh, Dd, 0, 0};
    k_mgemm<MP_H2, 1, HF><<<dim3(Dd / 128, SB / 128, 1), 256, SMM1>>>(p);
    k_gateln<<<SB, 256>>>(f_s, f_b);
    // FFN  (1-term, occ2)
    p = {p_olh, nullptr, p_w1h, nullptr, b1, nullptr, nullptr, nullptr, Dd, II, 0, 0};
    k_mgemm<MP_RELU, 1, HF><<<dim3(II / 128, SB / 128, 1), 256, SMM1>>>(p);
    p = {p_inh, nullptr, p_w2h, nullptr, b2, nullptr, nullptr, (float*)d_out, II, Dd, 0, 0};
    k_mgemm<MP_FIN, 1, HF><<<dim3(Dd / 128, SB / 128, 1), 256, SMM1>>>(p);
}